// round 12
// baseline (speedup 1.0000x reference)
#include <cuda_runtime.h>
#include <cuda_bf16.h>
#include <cstdint>

using bf16 = __nv_bfloat16;

// Problem dims
static constexpr int NB = 8, NS = 1024, ND = 512, NK = 64, NH = 8;

static constexpr size_t SZ_X  = (size_t)NB * NS * ND;          // 4,194,304
static constexpr size_t SZ_VT = (size_t)NB * (ND * NH) * NS;   // 33,554,432
static constexpr size_t SZ_O  = (size_t)NB * NS * (NH * ND);   // 33,554,432

// -------- static scratch (no runtime allocation allowed) --------
__device__ bf16  g_xb  [SZ_X];
__device__ bf16  g_qkb [SZ_X * 2];        // [8192][1024]: q cols 0-511, k cols 512-1023
__device__ bf16  g_wqkt[1024 * ND];       // [1024][512]  rows 0-511 WqT, 512-1023 WkT
__device__ bf16  g_wvt[(ND * NH) * ND];   // [4096][512] WvT
__device__ bf16  g_wot[ND * (ND * NH)];   // [512][4096] WoT
__device__ bf16  g_vt [SZ_VT];            // [b][4096][1024]  V^T per batch
__device__ bf16  g_ob [SZ_O];             // [8192][4096] attention output
__device__ float g_y  [SZ_X];             // pre-LN (o@Wo + bo + x)

// ---------------------------------------------------------------
__device__ __forceinline__ uint32_t pack_bf16(float lo, float hi) {
    return ((uint32_t)__bfloat16_as_ushort(__float2bfloat16(hi)) << 16) |
            (uint32_t)__bfloat16_as_ushort(__float2bfloat16(lo));
}

__device__ __forceinline__ float ex2f(float x) {
    float r;
    asm("ex2.approx.f32 %0, %1;" : "=f"(r) : "f"(x));
    return r;
}

__device__ __forceinline__ void mma16816(float* d, const uint32_t* a, const uint32_t* b) {
    asm volatile(
        "mma.sync.aligned.m16n8k16.row.col.f32.bf16.bf16.f32 "
        "{%0,%1,%2,%3}, {%4,%5,%6,%7}, {%8,%9}, {%0,%1,%2,%3};\n"
        : "+f"(d[0]), "+f"(d[1]), "+f"(d[2]), "+f"(d[3])
        : "r"(a[0]), "r"(a[1]), "r"(a[2]), "r"(a[3]), "r"(b[0]), "r"(b[1]));
}

// ldmatrix x4: loads 4 8x8 bf16 matrices; per-lane row address in shared.
__device__ __forceinline__ void ldsm_x4(uint32_t& r0, uint32_t& r1, uint32_t& r2, uint32_t& r3,
                                        const void* p) {
    uint32_t a = (uint32_t)__cvta_generic_to_shared(p);
    asm volatile("ldmatrix.sync.aligned.m8n8.x4.shared.b16 {%0,%1,%2,%3}, [%4];"
                 : "=r"(r0), "=r"(r1), "=r"(r2), "=r"(r3) : "r"(a));
}

__device__ __forceinline__ void cpasync16(void* s, const void* g) {
    uint32_t sa = (uint32_t)__cvta_generic_to_shared(s);
    asm volatile("cp.async.cg.shared.global [%0], [%1], 16;\n" :: "r"(sa), "l"(g));
}
__device__ __forceinline__ void cpcommit() { asm volatile("cp.async.commit_group;\n" ::: "memory"); }
__device__ __forceinline__ void cpwait0()  { asm volatile("cp.async.wait_group 0;\n" ::: "memory"); }
__device__ __forceinline__ void cpwait1()  { asm volatile("cp.async.wait_group 1;\n" ::: "memory"); }

// -------- elementwise convert fp32 -> bf16 --------
__global__ void f32_to_bf16_k(const float* __restrict__ in, bf16* __restrict__ out, int n) {
    int i = (blockIdx.x * blockDim.x + threadIdx.x) * 4;
    if (i >= n) return;
    float4 v = *reinterpret_cast<const float4*>(in + i);
    uint2 u;
    u.x = pack_bf16(v.x, v.y);
    u.y = pack_bf16(v.z, v.w);
    *reinterpret_cast<uint2*>(out + i) = u;
}

// -------- transpose + convert: out[c][r] = in[r][c] --------
__global__ void transpose_to_bf16(const float* __restrict__ in, bf16* __restrict__ out,
                                  int R, int C) {
    __shared__ float t[32][33];
    int c0 = blockIdx.x * 32, r0 = blockIdx.y * 32;
    int tx = threadIdx.x;
    for (int i = threadIdx.y; i < 32; i += 8)
        t[i][tx] = in[(size_t)(r0 + i) * C + c0 + tx];
    __syncthreads();
    for (int i = threadIdx.y; i < 32; i += 8)
        out[(size_t)(c0 + i) * R + r0 + tx] = __float2bfloat16(t[tx][i]);
}

// -------- generic batched bf16 GEMM (cp.async double-buffered, ldmatrix frags) --------
// C[m,n] = alpha * sum_k A[m,k] * B[n,k]
// MODE 1: bf16 store     MODE 2: fp32 store + bias[n] + resid[m,n]
#define BM 128
#define BN 128
#define BK 32
#define BKP 40   // padded smem row (bf16); 80B row stride -> ldmatrix conflict-free

template <int MODE>
__global__ __launch_bounds__(256, 2)
void gemm_bf16_tn(const bf16* __restrict__ A, const bf16* __restrict__ B,
                  void* __restrict__ Cv,
                  int M, int N, int Kd, int lda, int ldb, int ldc,
                  long long sA1, long long sA2, long long sB1, long long sB2,
                  long long sC1, long long sC2, int Z1,
                  float alpha, const float* __restrict__ bias,
                  const float* __restrict__ resid, int ldres) {
    int z = blockIdx.z;
    int z1 = z % Z1, z2 = z / Z1;
    A += (size_t)z1 * sA1 + (size_t)z2 * sA2;
    B += (size_t)z1 * sB1 + (size_t)z2 * sB2;
    long long coff = (long long)z1 * sC1 + (long long)z2 * sC2;

    __shared__ alignas(16) bf16 As[2][BM][BKP];
    __shared__ alignas(16) bf16 Bs[2][BN][BKP];

    int tid  = threadIdx.x;
    int warp = tid >> 5, lane = tid & 31;
    int wm = (warp & 1) * 64;
    int wn = (warp >> 1) * 32;
    int bm0 = blockIdx.y * BM;
    int bn0 = blockIdx.x * BN;

    float acc[4][4][4];
#pragma unroll
    for (int i = 0; i < 4; i++)
#pragma unroll
        for (int j = 0; j < 4; j++)
#pragma unroll
            for (int r = 0; r < 4; r++) acc[i][j][r] = 0.f;

    int lr = tid >> 2;
    int lc = (tid & 3) * 8;
    int rq = lane >> 2;
    int cq = lane & 3;
    int l16 = lane & 15, lhi = (lane >> 4) * 8;

#pragma unroll
    for (int i = 0; i < 2; i++) {
        int r = lr + i * 64;
        cpasync16(&As[0][r][lc], A + (size_t)(bm0 + r) * lda + lc);
        cpasync16(&Bs[0][r][lc], B + (size_t)(bn0 + r) * ldb + lc);
    }
    cpcommit();

    int p = 0;
    for (int kt = 0; kt < Kd; kt += BK, p ^= 1) {
        cpwait0();
        __syncthreads();
        if (kt + BK < Kd) {
            int np = p ^ 1;
#pragma unroll
            for (int i = 0; i < 2; i++) {
                int r = lr + i * 64;
                cpasync16(&As[np][r][lc], A + (size_t)(bm0 + r) * lda + kt + BK + lc);
                cpasync16(&Bs[np][r][lc], B + (size_t)(bn0 + r) * ldb + kt + BK + lc);
            }
            cpcommit();
        }

#pragma unroll
        for (int ks = 0; ks < 2; ks++) {
            int kk = ks * 16 + lhi;
            uint32_t afr[4][4];
#pragma unroll
            for (int i = 0; i < 4; i++)
                ldsm_x4(afr[i][0], afr[i][1], afr[i][2], afr[i][3],
                        &As[p][wm + i * 16 + l16][kk]);
            uint32_t bfr[4][2];
#pragma unroll
            for (int jp = 0; jp < 2; jp++) {
                uint32_t b0, b1, b2, b3;
                ldsm_x4(b0, b1, b2, b3, &Bs[p][wn + jp * 16 + l16][kk]);
                bfr[2 * jp][0] = b0; bfr[2 * jp][1] = b2;
                bfr[2 * jp + 1][0] = b1; bfr[2 * jp + 1][1] = b3;
            }
#pragma unroll
            for (int i = 0; i < 4; i++)
#pragma unroll
                for (int j = 0; j < 4; j++)
                    mma16816(acc[i][j], afr[i], bfr[j]);
        }
        __syncthreads();
    }

    int cq2 = cq * 2;
    float* Cf = (MODE == 1) ? nullptr : (float*)Cv + coff;
    bf16*  Cb = (MODE == 1) ? (bf16*)Cv + coff : nullptr;
#pragma unroll
    for (int i = 0; i < 4; i++) {
#pragma unroll
        for (int j = 0; j < 4; j++) {
            int row = bm0 + wm + i * 16 + rq;
            int col = bn0 + wn + j * 8 + cq2;
            float c0 = acc[i][j][0] * alpha, c1 = acc[i][j][1] * alpha;
            float c2 = acc[i][j][2] * alpha, c3 = acc[i][j][3] * alpha;
            if (MODE == 2) {
                float b0v = bias[col], b1v = bias[col + 1];
                const float* r0p = resid + (size_t)row * ldres + col;
                const float* r1p = resid + (size_t)(row + 8) * ldres + col;
                c0 += b0v + r0p[0]; c1 += b1v + r0p[1];
                c2 += b0v + r1p[0]; c3 += b1v + r1p[1];
            }
            if (MODE == 1) {
                *reinterpret_cast<uint32_t*>(Cb + (size_t)row * ldc + col)       = pack_bf16(c0, c1);
                *reinterpret_cast<uint32_t*>(Cb + (size_t)(row + 8) * ldc + col) = pack_bf16(c2, c3);
            } else {
                *reinterpret_cast<float2*>(Cf + (size_t)row * ldc + col)       = make_float2(c0, c1);
                *reinterpret_cast<float2*>(Cf + (size_t)(row + 8) * ldc + col) = make_float2(c2, c3);
            }
        }
    }
}

// ================================================================
// Fused flash attention, FA2-style warp layout + ldmatrix fragment
// loads. d-chunk = 256; exp2-domain softmax. Softmax ALU (exp2,
// packs, oacc rescale) is interleaved INTO the PV mma loop so it
// executes under the HMMA tensor-pipe shadow; rowsum reduction is
// deferred until after PV.
// Block: q-tile 128 x d-chunk 256 for one (b,h); 8 s-iters of 128.
// grid = (16, 64): x = dch*8 + qt (dch 0..1), y = b*8 + h.
// Smem: Q[128*72] | K[2][128*72] | V[2][256*136]   (~190 KB)
// ================================================================
#define SCALE_LOG2 0.18033688f   // 0.125 * log2(e)
static constexpr int FQS = 72;    // Q/K row stride bf16 (144B, conflict-free)
static constexpr int FVS = 136;   // V row stride bf16 (272B, conflict-free)
static constexpr int FLASH_SMEM = (128 * FQS * 3 + 2 * 256 * FVS) * 2;

__global__ __launch_bounds__(256, 1)
void flash_attn_k(const bf16* __restrict__ QKg, const bf16* __restrict__ Vg,
                  bf16* __restrict__ Og) {
    extern __shared__ __align__(16) char fsm[];
    bf16* Qs = (bf16*)fsm;           // 128*72
    bf16* Ks = Qs + 128 * FQS;       // 2 bufs of 128*72
    bf16* Vs = Ks + 2 * 128 * FQS;   // 2 bufs of 256*136

    int tid  = threadIdx.x;
    int warp = tid >> 5, lane = tid & 31;
    int rq = lane >> 2, cq = lane & 3, cq2 = cq << 1;
    int l16 = lane & 15, lhi = (lane >> 4) * 8;
    int w16 = warp * 16;
    int qt = blockIdx.x & 7, dch = blockIdx.x >> 3;   // dch 0..1
    int b  = blockIdx.y >> 3, h = blockIdx.y & 7;

    const bf16* Qp = QKg + ((size_t)(b * 1024 + qt * 128)) * 1024 + h * 64;
    const bf16* Kp = QKg + ((size_t)(b * 1024)) * 1024 + 512 + h * 64;
    const bf16* Vp = Vg + (size_t)b * 4194304 + ((size_t)(h * 512 + dch * 256)) * 1024;

#pragma unroll
    for (int p = 0; p < 4; p++) {
        int idx = tid + p * 256; int r = idx >> 3, c = (idx & 7) * 8;
        cpasync16(Qs + r * FQS + c, Qp + (size_t)r * 1024 + c);
    }
    cpcommit();
#pragma unroll
    for (int p = 0; p < 4; p++) {
        int idx = tid + p * 256; int r = idx >> 3, c = (idx & 7) * 8;
        cpasync16(Ks + r * FQS + c, Kp + (size_t)r * 1024 + c);
    }
#pragma unroll
    for (int p = 0; p < 16; p++) {
        int idx = tid + p * 256; int r = idx >> 4, c = (idx & 15) * 8;
        cpasync16(Vs + r * FVS + c, Vp + (size_t)r * 1024 + c);
    }
    cpcommit();

    cpwait1();
    __syncthreads();
    uint32_t qfr[4][4];
#pragma unroll
    for (int kg = 0; kg < 4; kg++)
        ldsm_x4(qfr[kg][0], qfr[kg][1], qfr[kg][2], qfr[kg][3],
                Qs + (w16 + l16) * FQS + kg * 16 + lhi);

    float oacc[32][4];
#pragma unroll
    for (int n = 0; n < 32; n++)
#pragma unroll
        for (int r = 0; r < 4; r++) oacc[n][r] = 0.f;
    float m0 = -1e30f, m1 = -1e30f, l0 = 0.f, l1 = 0.f;

    int cur = 0;
    for (int st = 0; st < 8; st++) {
        cpwait0();
        __syncthreads();
        if (st < 7) {
            int nb = cur ^ 1;
            int s1 = (st + 1) * 128;
#pragma unroll
            for (int p = 0; p < 4; p++) {
                int idx = tid + p * 256; int r = idx >> 3, c = (idx & 7) * 8;
                cpasync16(Ks + nb * 128 * FQS + r * FQS + c, Kp + (size_t)(s1 + r) * 1024 + c);
            }
#pragma unroll
            for (int p = 0; p < 16; p++) {
                int idx = tid + p * 256; int r = idx >> 4, c = (idx & 15) * 8;
                cpasync16(Vs + nb * 256 * FVS + r * FVS + c, Vp + (size_t)r * 1024 + s1 + c);
            }
            cpcommit();
        }

        // ---- S = Q·K^T : M=16 (warp rows), N=128, K=64 ----
        float sacc[16][4];
#pragma unroll
        for (int j = 0; j < 16; j++)
#pragma unroll
            for (int r = 0; r < 4; r++) sacc[j][r] = 0.f;

        const bf16* Kc = Ks + cur * 128 * FQS;
#pragma unroll
        for (int kg = 0; kg < 4; kg++) {
#pragma unroll
            for (int jp = 0; jp < 8; jp++) {
                uint32_t b0, b1, b2, b3;
                ldsm_x4(b0, b1, b2, b3, Kc + (jp * 16 + l16) * FQS + kg * 16 + lhi);
                uint32_t bfA[2] = {b0, b2}, bfB[2] = {b1, b3};
                mma16816(sacc[2 * jp],     qfr[kg], bfA);
                mma16816(sacc[2 * jp + 1], qfr[kg], bfB);
            }
        }

        // mask (raw==0) + scale into log2 domain (0.125*log2e)
#pragma unroll
        for (int j = 0; j < 16; j++)
#pragma unroll
            for (int r = 0; r < 4; r++) {
                float v = sacc[j][r];
                sacc[j][r] = (v == 0.f) ? -1e9f : v * SCALE_LOG2;
            }

        // ---- row max (quad shuffle only) ----
        float mx0 = -1e30f, mx1 = -1e30f;
#pragma unroll
        for (int j = 0; j < 16; j++) {
            mx0 = fmaxf(mx0, fmaxf(sacc[j][0], sacc[j][1]));
            mx1 = fmaxf(mx1, fmaxf(sacc[j][2], sacc[j][3]));
        }
        mx0 = fmaxf(mx0, __shfl_xor_sync(0xffffffffu, mx0, 1));
        mx0 = fmaxf(mx0, __shfl_xor_sync(0xffffffffu, mx0, 2));
        mx1 = fmaxf(mx1, __shfl_xor_sync(0xffffffffu, mx1, 1));
        mx1 = fmaxf(mx1, __shfl_xor_sync(0xffffffffu, mx1, 2));

        float nm0 = fmaxf(m0, mx0), nm1 = fmaxf(m1, mx1);
        float scf0 = ex2f(m0 - nm0), scf1 = ex2f(m1 - nm1);
        m0 = nm0; m1 = nm1;

        // ---- fused P-compute + O rescale + PV mma ----
        // P (exp2), packs, and oacc rescale issue in the HMMA shadow.
        float rs0 = 0.f, rs1 = 0.f;
        const bf16* Vc = Vs + cur * 256 * FVS;
#pragma unroll
        for (int kg = 0; kg < 8; kg++) {
            int j0 = 2 * kg, j1 = 2 * kg + 1;
            float e00 = ex2f(sacc[j0][0] - m0), e01 = ex2f(sacc[j0][1] - m0);
            float e02 = ex2f(sacc[j0][2] - m1), e03 = ex2f(sacc[j0][3] - m1);
            float e10 = ex2f(sacc[j1][0] - m0), e11 = ex2f(sacc[j1][1] - m0);
            float e12 = ex2f(sacc[j1][2] - m1), e13 = ex2f(sacc[j1][3] - m1);
            rs0 += e00 + e01 + e10 + e11;
            rs1 += e02 + e03 + e12 + e13;
            uint32_t pf[4];
            pf[0] = pack_bf16(e00, e01);
            pf[1] = pack_bf16(e02, e03);
            pf[2] = pack_bf16(e10, e11);
            pf[3] = pack_bf16(e12, e13);
#pragma unroll
            for (int np = 0; np < 16; np++) {
                if (kg == 0) {
                    oacc[2 * np][0] *= scf0; oacc[2 * np][1] *= scf0;
                    oacc[2 * np][2] *= scf1; oacc[2 * np][3] *= scf1;
                    oacc[2 * np + 1][0] *= scf0; oacc[2 * np + 1][1] *= scf0;
                    oacc[2 * np + 1][2] *= scf1; oacc[2 * np + 1][3] *= scf1;
                }
                uint32_t b0, b1, b2, b3;
                ldsm_x4(b0, b1, b2, b3, Vc + (np * 16 + l16) * FVS + kg * 16 + lhi);
                uint32_t bfA[2] = {b0, b2}, bfB[2] = {b1, b3};
                mma16816(oacc[2 * np],     pf, bfA);
                uint32_t pfB[4] = {pf[2], pf[3], pf[0], pf[1]};
                // NOTE: A-fragment order for row-halves is {lo, hi} pairs:
                // oacc[2np+1] uses the same pf (rows are encoded inside frag).
                mma16816(oacc[2 * np + 1], pf, bfB);
                (void)pfB;
            }
        }

        // deferred rowsum reduce + l update
        rs0 += __shfl_xor_sync(0xffffffffu, rs0, 1);
        rs0 += __shfl_xor_sync(0xffffffffu, rs0, 2);
        rs1 += __shfl_xor_sync(0xffffffffu, rs1, 1);
        rs1 += __shfl_xor_sync(0xffffffffu, rs1, 2);
        l0 = l0 * scf0 + rs0;
        l1 = l1 * scf1 + rs1;

        cur ^= 1;
    }

    // ---- epilogue: O / l -> ob (bf16) ----
    float inv0 = 1.f / l0, inv1 = 1.f / l1;
    int row = b * 1024 + qt * 128 + w16 + rq;
    int colb = h * 512 + dch * 256 + cq2;
#pragma unroll
    for (int n = 0; n < 32; n++) {
        int col = colb + n * 8;
        *reinterpret_cast<uint32_t*>(Og + (size_t)row * 4096 + col) =
            pack_bf16(oacc[n][0] * inv0, oacc[n][1] * inv0);
        *reinterpret_cast<uint32_t*>(Og + (size_t)(row + 8) * 4096 + col) =
            pack_bf16(oacc[n][2] * inv1, oacc[n][3] * inv1);
    }
}

// -------- LayerNorm over D=512, eps=1e-6 --------
__global__ void layernorm_k(const float* __restrict__ y, const float* __restrict__ gamma,
                            const float* __restrict__ beta, float* __restrict__ out) {
    int row = blockIdx.x;
    int t = threadIdx.x;
    const float4* p = reinterpret_cast<const float4*>(y + (size_t)row * 512);
    float4 v = p[t];
    float s = v.x + v.y + v.z + v.w;
#pragma unroll
    for (int o = 16; o; o >>= 1) s += __shfl_xor_sync(0xffffffffu, s, o);
    __shared__ float sm[4];
    if ((t & 31) == 0) sm[t >> 5] = s;
    __syncthreads();
    float mu = (sm[0] + sm[1] + sm[2] + sm[3]) * (1.0f / 512.0f);
    float dx = v.x - mu, dy = v.y - mu, dz = v.z - mu, dw = v.w - mu;
    float q = dx * dx + dy * dy + dz * dz + dw * dw;
#pragma unroll
    for (int o = 16; o; o >>= 1) q += __shfl_xor_sync(0xffffffffu, q, o);
    __shared__ float sq[4];
    if ((t & 31) == 0) sq[t >> 5] = q;
    __syncthreads();
    float var = (sq[0] + sq[1] + sq[2] + sq[3]) * (1.0f / 512.0f);
    float rs = rsqrtf(var + 1e-6f);
    float4 g = reinterpret_cast<const float4*>(gamma)[t];
    float4 b = reinterpret_cast<const float4*>(beta)[t];
    float4 r;
    r.x = dx * rs * g.x + b.x;
    r.y = dy * rs * g.y + b.y;
    r.z = dz * rs * g.z + b.z;
    r.w = dw * rs * g.w + b.w;
    reinterpret_cast<float4*>(out + (size_t)row * 512)[t] = r;
}

// ---------------------------------------------------------------
extern "C" void kernel_launch(void* const* d_in, const int* in_sizes, int n_in,
                              void* d_out, int out_size) {
    const float* x     = (const float*)d_in[0];
    const float* Wq    = (const float*)d_in[1];
    const float* Wk    = (const float*)d_in[2];
    const float* Wv    = (const float*)d_in[3];
    const float* Wo    = (const float*)d_in[4];
    const float* bo    = (const float*)d_in[5];
    const float* gamma = (const float*)d_in[6];
    const float* beta  = (const float*)d_in[7];
    float* out = (float*)d_out;

    bf16 *xb, *qkb, *wqkt, *wvt, *wot, *vt, *ob;
    float *yb;
    cudaGetSymbolAddress((void**)&xb,   g_xb);
    cudaGetSymbolAddress((void**)&qkb,  g_qkb);
    cudaGetSymbolAddress((void**)&wqkt, g_wqkt);
    cudaGetSymbolAddress((void**)&wvt,  g_wvt);
    cudaGetSymbolAddress((void**)&wot,  g_wot);
    cudaGetSymbolAddress((void**)&vt,   g_vt);
    cudaGetSymbolAddress((void**)&ob,   g_ob);
    cudaGetSymbolAddress((void**)&yb,   g_y);

    cudaFuncSetAttribute(flash_attn_k, cudaFuncAttributeMaxDynamicSharedMemorySize, FLASH_SMEM);

    // 1) x -> bf16
    f32_to_bf16_k<<<(int)(SZ_X / 4 / 256), 256>>>(x, xb, (int)SZ_X);
    // 2) transposed bf16 weights (Wq and Wk into one concatenated buffer)
    transpose_to_bf16<<<dim3(16, 16),  dim3(32, 8)>>>(Wq, wqkt, 512, 512);
    transpose_to_bf16<<<dim3(16, 16),  dim3(32, 8)>>>(Wk, wqkt + 512 * 512, 512, 512);
    transpose_to_bf16<<<dim3(128, 16), dim3(32, 8)>>>(Wv, wvt, 512, 4096);
    transpose_to_bf16<<<dim3(16, 128), dim3(32, 8)>>>(Wo, wot, 4096, 512);

    // 3) [q|k] = x @ [Wq|Wk]   [8192,1024]
    gemm_bf16_tn<1><<<dim3(8, 64, 1), 256>>>(xb, wqkt, qkb, 8192, 1024, 512,
        512, 512, 1024, 0, 0, 0, 0, 0, 0, 1, 1.0f, nullptr, nullptr, 0);
    // 4) Vt[b] = WvT @ x[b]^T  -> [b][4096][1024]
    gemm_bf16_tn<1><<<dim3(8, 32, 8), 256>>>(wvt, xb, vt, 4096, 1024, 512,
        512, 512, 1024, 0, 0, 0, 524288LL, 0, 4194304LL, 1, 1.0f, nullptr, nullptr, 0);
    // 5) fused attention: scores + mask + softmax + P·V -> ob  (d-chunk 256)
    flash_attn_k<<<dim3(16, 64), 256, FLASH_SMEM>>>(qkb, vt, ob);
    // 6) y = o @ Wo + bo + x
    gemm_bf16_tn<2><<<dim3(4, 64, 1), 256>>>(ob, wot, yb, 8192, 512, 4096,
        4096, 4096, 512, 0, 0, 0, 0, 0, 0, 1, 1.0f, bo, x, 512);
    // 7) LayerNorm -> out
    layernorm_k<<<8192, 128>>>(yb, gamma, beta, out);
}

// round 15
// speedup vs baseline: 1.0459x; 1.0459x over previous
#include <cuda_runtime.h>
#include <cuda_bf16.h>
#include <cstdint>

using bf16 = __nv_bfloat16;

// Problem dims
static constexpr int NB = 8, NS = 1024, ND = 512, NK = 64, NH = 8;

static constexpr size_t SZ_X  = (size_t)NB * NS * ND;          // 4,194,304
static constexpr size_t SZ_VT = (size_t)NB * (ND * NH) * NS;   // 33,554,432
static constexpr size_t SZ_O  = (size_t)NB * NS * (NH * ND);   // 33,554,432

// -------- static scratch (no runtime allocation allowed) --------
__device__ bf16  g_xb  [SZ_X];
__device__ bf16  g_qkb [SZ_X * 2];        // [8192][1024]: q cols 0-511, k cols 512-1023
__device__ bf16  g_wqkt[1024 * ND];       // [1024][512]  rows 0-511 WqT, 512-1023 WkT
__device__ bf16  g_wvt[(ND * NH) * ND];   // [4096][512] WvT
__device__ bf16  g_wot[ND * (ND * NH)];   // [512][4096] WoT
__device__ bf16  g_vt [SZ_VT];            // [b][4096][1024]  V^T per batch
__device__ bf16  g_ob [SZ_O];             // [8192][4096] attention output
__device__ float g_y  [SZ_X];             // pre-LN (o@Wo + bo + x)

// ---------------------------------------------------------------
__device__ __forceinline__ uint32_t pack_bf16(float lo, float hi) {
    return ((uint32_t)__bfloat16_as_ushort(__float2bfloat16(hi)) << 16) |
            (uint32_t)__bfloat16_as_ushort(__float2bfloat16(lo));
}

__device__ __forceinline__ float ex2f(float x) {
    float r;
    asm("ex2.approx.f32 %0, %1;" : "=f"(r) : "f"(x));
    return r;
}

__device__ __forceinline__ void mma16816(float* d, const uint32_t* a, const uint32_t* b) {
    asm volatile(
        "mma.sync.aligned.m16n8k16.row.col.f32.bf16.bf16.f32 "
        "{%0,%1,%2,%3}, {%4,%5,%6,%7}, {%8,%9}, {%0,%1,%2,%3};\n"
        : "+f"(d[0]), "+f"(d[1]), "+f"(d[2]), "+f"(d[3])
        : "r"(a[0]), "r"(a[1]), "r"(a[2]), "r"(a[3]), "r"(b[0]), "r"(b[1]));
}

// ldmatrix x4: loads 4 8x8 bf16 matrices; per-lane row address in shared.
__device__ __forceinline__ void ldsm_x4(uint32_t& r0, uint32_t& r1, uint32_t& r2, uint32_t& r3,
                                        const void* p) {
    uint32_t a = (uint32_t)__cvta_generic_to_shared(p);
    asm volatile("ldmatrix.sync.aligned.m8n8.x4.shared.b16 {%0,%1,%2,%3}, [%4];"
                 : "=r"(r0), "=r"(r1), "=r"(r2), "=r"(r3) : "r"(a));
}

__device__ __forceinline__ void cpasync16(void* s, const void* g) {
    uint32_t sa = (uint32_t)__cvta_generic_to_shared(s);
    asm volatile("cp.async.cg.shared.global [%0], [%1], 16;\n" :: "r"(sa), "l"(g));
}
__device__ __forceinline__ void cpcommit() { asm volatile("cp.async.commit_group;\n" ::: "memory"); }
__device__ __forceinline__ void cpwait0()  { asm volatile("cp.async.wait_group 0;\n" ::: "memory"); }
__device__ __forceinline__ void cpwait1()  { asm volatile("cp.async.wait_group 1;\n" ::: "memory"); }

// -------- elementwise convert fp32 -> bf16 --------
__global__ void f32_to_bf16_k(const float* __restrict__ in, bf16* __restrict__ out, int n) {
    int i = (blockIdx.x * blockDim.x + threadIdx.x) * 4;
    if (i >= n) return;
    float4 v = *reinterpret_cast<const float4*>(in + i);
    uint2 u;
    u.x = pack_bf16(v.x, v.y);
    u.y = pack_bf16(v.z, v.w);
    *reinterpret_cast<uint2*>(out + i) = u;
}

// -------- transpose + convert: out[c][r] = in[r][c] --------
__global__ void transpose_to_bf16(const float* __restrict__ in, bf16* __restrict__ out,
                                  int R, int C) {
    __shared__ float t[32][33];
    int c0 = blockIdx.x * 32, r0 = blockIdx.y * 32;
    int tx = threadIdx.x;
    for (int i = threadIdx.y; i < 32; i += 8)
        t[i][tx] = in[(size_t)(r0 + i) * C + c0 + tx];
    __syncthreads();
    for (int i = threadIdx.y; i < 32; i += 8)
        out[(size_t)(c0 + i) * R + r0 + tx] = __float2bfloat16(t[tx][i]);
}

// -------- generic batched bf16 GEMM (cp.async double-buffered, ldmatrix frags) --------
// C[m,n] = alpha * sum_k A[m,k] * B[n,k]
// MODE 1: bf16 store     MODE 2: fp32 store + bias[n] + resid[m,n]
#define BM 128
#define BN 128
#define BK 32
#define BKP 40   // padded smem row (bf16); 80B row stride -> ldmatrix conflict-free

template <int MODE>
__global__ __launch_bounds__(256, 2)
void gemm_bf16_tn(const bf16* __restrict__ A, const bf16* __restrict__ B,
                  void* __restrict__ Cv,
                  int M, int N, int Kd, int lda, int ldb, int ldc,
                  long long sA1, long long sA2, long long sB1, long long sB2,
                  long long sC1, long long sC2, int Z1,
                  float alpha, const float* __restrict__ bias,
                  const float* __restrict__ resid, int ldres) {
    int z = blockIdx.z;
    int z1 = z % Z1, z2 = z / Z1;
    A += (size_t)z1 * sA1 + (size_t)z2 * sA2;
    B += (size_t)z1 * sB1 + (size_t)z2 * sB2;
    long long coff = (long long)z1 * sC1 + (long long)z2 * sC2;

    __shared__ alignas(16) bf16 As[2][BM][BKP];
    __shared__ alignas(16) bf16 Bs[2][BN][BKP];

    int tid  = threadIdx.x;
    int warp = tid >> 5, lane = tid & 31;
    int wm = (warp & 1) * 64;
    int wn = (warp >> 1) * 32;
    int bm0 = blockIdx.y * BM;
    int bn0 = blockIdx.x * BN;

    float acc[4][4][4];
#pragma unroll
    for (int i = 0; i < 4; i++)
#pragma unroll
        for (int j = 0; j < 4; j++)
#pragma unroll
            for (int r = 0; r < 4; r++) acc[i][j][r] = 0.f;

    int lr = tid >> 2;
    int lc = (tid & 3) * 8;
    int rq = lane >> 2;
    int cq = lane & 3;
    int l16 = lane & 15, lhi = (lane >> 4) * 8;

#pragma unroll
    for (int i = 0; i < 2; i++) {
        int r = lr + i * 64;
        cpasync16(&As[0][r][lc], A + (size_t)(bm0 + r) * lda + lc);
        cpasync16(&Bs[0][r][lc], B + (size_t)(bn0 + r) * ldb + lc);
    }
    cpcommit();

    int p = 0;
    for (int kt = 0; kt < Kd; kt += BK, p ^= 1) {
        cpwait0();
        __syncthreads();
        if (kt + BK < Kd) {
            int np = p ^ 1;
#pragma unroll
            for (int i = 0; i < 2; i++) {
                int r = lr + i * 64;
                cpasync16(&As[np][r][lc], A + (size_t)(bm0 + r) * lda + kt + BK + lc);
                cpasync16(&Bs[np][r][lc], B + (size_t)(bn0 + r) * ldb + kt + BK + lc);
            }
            cpcommit();
        }

#pragma unroll
        for (int ks = 0; ks < 2; ks++) {
            int kk = ks * 16 + lhi;
            uint32_t afr[4][4];
#pragma unroll
            for (int i = 0; i < 4; i++)
                ldsm_x4(afr[i][0], afr[i][1], afr[i][2], afr[i][3],
                        &As[p][wm + i * 16 + l16][kk]);
            uint32_t bfr[4][2];
#pragma unroll
            for (int jp = 0; jp < 2; jp++) {
                uint32_t b0, b1, b2, b3;
                ldsm_x4(b0, b1, b2, b3, &Bs[p][wn + jp * 16 + l16][kk]);
                bfr[2 * jp][0] = b0; bfr[2 * jp][1] = b2;
                bfr[2 * jp + 1][0] = b1; bfr[2 * jp + 1][1] = b3;
            }
#pragma unroll
            for (int i = 0; i < 4; i++)
#pragma unroll
                for (int j = 0; j < 4; j++)
                    mma16816(acc[i][j], afr[i], bfr[j]);
        }
        __syncthreads();
    }

    int cq2 = cq * 2;
    float* Cf = (MODE == 1) ? nullptr : (float*)Cv + coff;
    bf16*  Cb = (MODE == 1) ? (bf16*)Cv + coff : nullptr;
#pragma unroll
    for (int i = 0; i < 4; i++) {
#pragma unroll
        for (int j = 0; j < 4; j++) {
            int row = bm0 + wm + i * 16 + rq;
            int col = bn0 + wn + j * 8 + cq2;
            float c0 = acc[i][j][0] * alpha, c1 = acc[i][j][1] * alpha;
            float c2 = acc[i][j][2] * alpha, c3 = acc[i][j][3] * alpha;
            if (MODE == 2) {
                float b0v = bias[col], b1v = bias[col + 1];
                const float* r0p = resid + (size_t)row * ldres + col;
                const float* r1p = resid + (size_t)(row + 8) * ldres + col;
                c0 += b0v + r0p[0]; c1 += b1v + r0p[1];
                c2 += b0v + r1p[0]; c3 += b1v + r1p[1];
            }
            if (MODE == 1) {
                *reinterpret_cast<uint32_t*>(Cb + (size_t)row * ldc + col)       = pack_bf16(c0, c1);
                *reinterpret_cast<uint32_t*>(Cb + (size_t)(row + 8) * ldc + col) = pack_bf16(c2, c3);
            } else {
                *reinterpret_cast<float2*>(Cf + (size_t)row * ldc + col)       = make_float2(c0, c1);
                *reinterpret_cast<float2*>(Cf + (size_t)(row + 8) * ldc + col) = make_float2(c2, c3);
            }
        }
    }
}

// ================================================================
// Fused flash attention (R11-validated ordering: batched exp2 before
// the PV mma block so ptxas can software-pipeline; rowsum reduce
// deferred to after PV). d-chunk = 256; exp2-domain softmax.
// Block: q-tile 128 x d-chunk 256 for one (b,h); 8 s-iters of 128.
// grid = (16, 64): x = dch*8 + qt (dch 0..1), y = b*8 + h.
// Smem: Q[128*72] | K[2][128*72] | V[2][256*136]   (~190 KB)
// ================================================================
#define SCALE_LOG2 0.18033688f   // 0.125 * log2(e)
static constexpr int FQS = 72;    // Q/K row stride bf16 (144B, conflict-free)
static constexpr int FVS = 136;   // V row stride bf16 (272B, conflict-free)
static constexpr int FLASH_SMEM = (128 * FQS * 3 + 2 * 256 * FVS) * 2;

__global__ __launch_bounds__(256, 1)
void flash_attn_k(const bf16* __restrict__ QKg, const bf16* __restrict__ Vg,
                  bf16* __restrict__ Og) {
    extern __shared__ __align__(16) char fsm[];
    bf16* Qs = (bf16*)fsm;           // 128*72
    bf16* Ks = Qs + 128 * FQS;       // 2 bufs of 128*72
    bf16* Vs = Ks + 2 * 128 * FQS;   // 2 bufs of 256*136

    int tid  = threadIdx.x;
    int warp = tid >> 5, lane = tid & 31;
    int rq = lane >> 2, cq = lane & 3, cq2 = cq << 1;
    int l16 = lane & 15, lhi = (lane >> 4) * 8;
    int w16 = warp * 16;
    int qt = blockIdx.x & 7, dch = blockIdx.x >> 3;   // dch 0..1
    int b  = blockIdx.y >> 3, h = blockIdx.y & 7;

    const bf16* Qp = QKg + ((size_t)(b * 1024 + qt * 128)) * 1024 + h * 64;
    const bf16* Kp = QKg + ((size_t)(b * 1024)) * 1024 + 512 + h * 64;
    const bf16* Vp = Vg + (size_t)b * 4194304 + ((size_t)(h * 512 + dch * 256)) * 1024;

#pragma unroll
    for (int p = 0; p < 4; p++) {
        int idx = tid + p * 256; int r = idx >> 3, c = (idx & 7) * 8;
        cpasync16(Qs + r * FQS + c, Qp + (size_t)r * 1024 + c);
    }
    cpcommit();
#pragma unroll
    for (int p = 0; p < 4; p++) {
        int idx = tid + p * 256; int r = idx >> 3, c = (idx & 7) * 8;
        cpasync16(Ks + r * FQS + c, Kp + (size_t)r * 1024 + c);
    }
#pragma unroll
    for (int p = 0; p < 16; p++) {
        int idx = tid + p * 256; int r = idx >> 4, c = (idx & 15) * 8;
        cpasync16(Vs + r * FVS + c, Vp + (size_t)r * 1024 + c);
    }
    cpcommit();

    cpwait1();
    __syncthreads();
    uint32_t qfr[4][4];
#pragma unroll
    for (int kg = 0; kg < 4; kg++)
        ldsm_x4(qfr[kg][0], qfr[kg][1], qfr[kg][2], qfr[kg][3],
                Qs + (w16 + l16) * FQS + kg * 16 + lhi);

    float oacc[32][4];
#pragma unroll
    for (int n = 0; n < 32; n++)
#pragma unroll
        for (int r = 0; r < 4; r++) oacc[n][r] = 0.f;
    float m0 = -1e30f, m1 = -1e30f, l0 = 0.f, l1 = 0.f;

    int cur = 0;
    for (int st = 0; st < 8; st++) {
        cpwait0();
        __syncthreads();
        if (st < 7) {
            int nb = cur ^ 1;
            int s1 = (st + 1) * 128;
#pragma unroll
            for (int p = 0; p < 4; p++) {
                int idx = tid + p * 256; int r = idx >> 3, c = (idx & 7) * 8;
                cpasync16(Ks + nb * 128 * FQS + r * FQS + c, Kp + (size_t)(s1 + r) * 1024 + c);
            }
#pragma unroll
            for (int p = 0; p < 16; p++) {
                int idx = tid + p * 256; int r = idx >> 4, c = (idx & 15) * 8;
                cpasync16(Vs + nb * 256 * FVS + r * FVS + c, Vp + (size_t)r * 1024 + s1 + c);
            }
            cpcommit();
        }

        // ---- S = Q·K^T : M=16 (warp rows), N=128, K=64 ----
        float sacc[16][4];
#pragma unroll
        for (int j = 0; j < 16; j++)
#pragma unroll
            for (int r = 0; r < 4; r++) sacc[j][r] = 0.f;

        const bf16* Kc = Ks + cur * 128 * FQS;
#pragma unroll
        for (int kg = 0; kg < 4; kg++) {
#pragma unroll
            for (int jp = 0; jp < 8; jp++) {
                uint32_t b0, b1, b2, b3;
                ldsm_x4(b0, b1, b2, b3, Kc + (jp * 16 + l16) * FQS + kg * 16 + lhi);
                uint32_t bfA[2] = {b0, b2}, bfB[2] = {b1, b3};
                mma16816(sacc[2 * jp],     qfr[kg], bfA);
                mma16816(sacc[2 * jp + 1], qfr[kg], bfB);
            }
        }

        // mask (raw==0) + scale into log2 domain (0.125*log2e)
#pragma unroll
        for (int j = 0; j < 16; j++)
#pragma unroll
            for (int r = 0; r < 4; r++) {
                float v = sacc[j][r];
                sacc[j][r] = (v == 0.f) ? -1e9f : v * SCALE_LOG2;
            }

        // ---- row max (quad shuffle only) ----
        float mx0 = -1e30f, mx1 = -1e30f;
#pragma unroll
        for (int j = 0; j < 16; j++) {
            mx0 = fmaxf(mx0, fmaxf(sacc[j][0], sacc[j][1]));
            mx1 = fmaxf(mx1, fmaxf(sacc[j][2], sacc[j][3]));
        }
        mx0 = fmaxf(mx0, __shfl_xor_sync(0xffffffffu, mx0, 1));
        mx0 = fmaxf(mx0, __shfl_xor_sync(0xffffffffu, mx0, 2));
        mx1 = fmaxf(mx1, __shfl_xor_sync(0xffffffffu, mx1, 1));
        mx1 = fmaxf(mx1, __shfl_xor_sync(0xffffffffu, mx1, 2));

        float nm0 = fmaxf(m0, mx0), nm1 = fmaxf(m1, mx1);
        float scf0 = ex2f(m0 - nm0), scf1 = ex2f(m1 - nm1);
        m0 = nm0; m1 = nm1;

#pragma unroll
        for (int n = 0; n < 32; n++) {
            oacc[n][0] *= scf0; oacc[n][1] *= scf0;
            oacc[n][2] *= scf1; oacc[n][3] *= scf1;
        }

        // ---- P = exp2(S' - m') in registers (batched; reduce deferred) ----
        uint32_t pf[8][4];
        float rs0 = 0.f, rs1 = 0.f;
#pragma unroll
        for (int kg = 0; kg < 8; kg++) {
            int j0 = 2 * kg, j1 = 2 * kg + 1;
            float e00 = ex2f(sacc[j0][0] - m0), e01 = ex2f(sacc[j0][1] - m0);
            float e02 = ex2f(sacc[j0][2] - m1), e03 = ex2f(sacc[j0][3] - m1);
            float e10 = ex2f(sacc[j1][0] - m0), e11 = ex2f(sacc[j1][1] - m0);
            float e12 = ex2f(sacc[j1][2] - m1), e13 = ex2f(sacc[j1][3] - m1);
            rs0 += e00 + e01 + e10 + e11;
            rs1 += e02 + e03 + e12 + e13;
            pf[kg][0] = pack_bf16(e00, e01);
            pf[kg][1] = pack_bf16(e02, e03);
            pf[kg][2] = pack_bf16(e10, e11);
            pf[kg][3] = pack_bf16(e12, e13);
        }

        // ---- O += P·V : M=16, N=256 (d), K=128 (s) ----
        const bf16* Vc = Vs + cur * 256 * FVS;
#pragma unroll
        for (int kg = 0; kg < 8; kg++) {
#pragma unroll
            for (int np = 0; np < 16; np++) {
                uint32_t b0, b1, b2, b3;
                ldsm_x4(b0, b1, b2, b3, Vc + (np * 16 + l16) * FVS + kg * 16 + lhi);
                uint32_t bfA[2] = {b0, b2}, bfB[2] = {b1, b3};
                mma16816(oacc[2 * np],     pf[kg], bfA);
                mma16816(oacc[2 * np + 1], pf[kg], bfB);
            }
        }

        // deferred rowsum reduce + l update (shadowed by PV mma drain)
        rs0 += __shfl_xor_sync(0xffffffffu, rs0, 1);
        rs0 += __shfl_xor_sync(0xffffffffu, rs0, 2);
        rs1 += __shfl_xor_sync(0xffffffffu, rs1, 1);
        rs1 += __shfl_xor_sync(0xffffffffu, rs1, 2);
        l0 = l0 * scf0 + rs0;
        l1 = l1 * scf1 + rs1;

        cur ^= 1;
    }

    // ---- epilogue: O / l -> ob (bf16) ----
    float inv0 = 1.f / l0, inv1 = 1.f / l1;
    int row = b * 1024 + qt * 128 + w16 + rq;
    int colb = h * 512 + dch * 256 + cq2;
#pragma unroll
    for (int n = 0; n < 32; n++) {
        int col = colb + n * 8;
        *reinterpret_cast<uint32_t*>(Og + (size_t)row * 4096 + col) =
            pack_bf16(oacc[n][0] * inv0, oacc[n][1] * inv0);
        *reinterpret_cast<uint32_t*>(Og + (size_t)(row + 8) * 4096 + col) =
            pack_bf16(oacc[n][2] * inv1, oacc[n][3] * inv1);
    }
}

// -------- LayerNorm over D=512, eps=1e-6 --------
__global__ void layernorm_k(const float* __restrict__ y, const float* __restrict__ gamma,
                            const float* __restrict__ beta, float* __restrict__ out) {
    int row = blockIdx.x;
    int t = threadIdx.x;
    const float4* p = reinterpret_cast<const float4*>(y + (size_t)row * 512);
    float4 v = p[t];
    float s = v.x + v.y + v.z + v.w;
#pragma unroll
    for (int o = 16; o; o >>= 1) s += __shfl_xor_sync(0xffffffffu, s, o);
    __shared__ float sm[4];
    if ((t & 31) == 0) sm[t >> 5] = s;
    __syncthreads();
    float mu = (sm[0] + sm[1] + sm[2] + sm[3]) * (1.0f / 512.0f);
    float dx = v.x - mu, dy = v.y - mu, dz = v.z - mu, dw = v.w - mu;
    float q = dx * dx + dy * dy + dz * dz + dw * dw;
#pragma unroll
    for (int o = 16; o; o >>= 1) q += __shfl_xor_sync(0xffffffffu, q, o);
    __shared__ float sq[4];
    if ((t & 31) == 0) sq[t >> 5] = q;
    __syncthreads();
    float var = (sq[0] + sq[1] + sq[2] + sq[3]) * (1.0f / 512.0f);
    float rs = rsqrtf(var + 1e-6f);
    float4 g = reinterpret_cast<const float4*>(gamma)[t];
    float4 b = reinterpret_cast<const float4*>(beta)[t];
    float4 r;
    r.x = dx * rs * g.x + b.x;
    r.y = dy * rs * g.y + b.y;
    r.z = dz * rs * g.z + b.z;
    r.w = dw * rs * g.w + b.w;
    reinterpret_cast<float4*>(out + (size_t)row * 512)[t] = r;
}

// ---------------------------------------------------------------
extern "C" void kernel_launch(void* const* d_in, const int* in_sizes, int n_in,
                              void* d_out, int out_size) {
    const float* x     = (const float*)d_in[0];
    const float* Wq    = (const float*)d_in[1];
    const float* Wk    = (const float*)d_in[2];
    const float* Wv    = (const float*)d_in[3];
    const float* Wo    = (const float*)d_in[4];
    const float* bo    = (const float*)d_in[5];
    const float* gamma = (const float*)d_in[6];
    const float* beta  = (const float*)d_in[7];
    float* out = (float*)d_out;

    bf16 *xb, *qkb, *wqkt, *wvt, *wot, *vt, *ob;
    float *yb;
    cudaGetSymbolAddress((void**)&xb,   g_xb);
    cudaGetSymbolAddress((void**)&qkb,  g_qkb);
    cudaGetSymbolAddress((void**)&wqkt, g_wqkt);
    cudaGetSymbolAddress((void**)&wvt,  g_wvt);
    cudaGetSymbolAddress((void**)&wot,  g_wot);
    cudaGetSymbolAddress((void**)&vt,   g_vt);
    cudaGetSymbolAddress((void**)&ob,   g_ob);
    cudaGetSymbolAddress((void**)&yb,   g_y);

    cudaFuncSetAttribute(flash_attn_k, cudaFuncAttributeMaxDynamicSharedMemorySize, FLASH_SMEM);

    // 1) x -> bf16
    f32_to_bf16_k<<<(int)(SZ_X / 4 / 256), 256>>>(x, xb, (int)SZ_X);
    // 2) transposed bf16 weights (Wq and Wk into one concatenated buffer)
    transpose_to_bf16<<<dim3(16, 16),  dim3(32, 8)>>>(Wq, wqkt, 512, 512);
    transpose_to_bf16<<<dim3(16, 16),  dim3(32, 8)>>>(Wk, wqkt + 512 * 512, 512, 512);
    transpose_to_bf16<<<dim3(128, 16), dim3(32, 8)>>>(Wv, wvt, 512, 4096);
    transpose_to_bf16<<<dim3(16, 128), dim3(32, 8)>>>(Wo, wot, 4096, 512);

    // 3) [q|k] = x @ [Wq|Wk]   [8192,1024]
    gemm_bf16_tn<1><<<dim3(8, 64, 1), 256>>>(xb, wqkt, qkb, 8192, 1024, 512,
        512, 512, 1024, 0, 0, 0, 0, 0, 0, 1, 1.0f, nullptr, nullptr, 0);
    // 4) Vt[b] = WvT @ x[b]^T  -> [b][4096][1024]
    gemm_bf16_tn<1><<<dim3(8, 32, 8), 256>>>(wvt, xb, vt, 4096, 1024, 512,
        512, 512, 1024, 0, 0, 0, 524288LL, 0, 4194304LL, 1, 1.0f, nullptr, nullptr, 0);
    // 5) fused attention: scores + mask + softmax + P·V -> ob  (d-chunk 256)
    flash_attn_k<<<dim3(16, 64), 256, FLASH_SMEM>>>(qkb, vt, ob);
    // 6) y = o @ Wo + bo + x
    gemm_bf16_tn<2><<<dim3(4, 64, 1), 256>>>(ob, wot, yb, 8192, 512, 4096,
        4096, 4096, 512, 0, 0, 0, 0, 0, 0, 1, 1.0f, bo, x, 512);
    // 7) LayerNorm -> out
    layernorm_k<<<8192, 128>>>(yb, gamma, beta, out);
}

// round 16
// speedup vs baseline: 1.1092x; 1.0605x over previous
#include <cuda_runtime.h>
#include <cuda_bf16.h>
#include <cstdint>

using bf16 = __nv_bfloat16;

// Problem dims
static constexpr int NB = 8, NS = 1024, ND = 512, NK = 64, NH = 8;

static constexpr size_t SZ_X  = (size_t)NB * NS * ND;          // 4,194,304
static constexpr size_t SZ_VT = (size_t)NB * (ND * NH) * NS;   // 33,554,432
static constexpr size_t SZ_O  = (size_t)NB * NS * (NH * ND);   // 33,554,432

// -------- static scratch (no runtime allocation allowed) --------
__device__ bf16  g_xb  [SZ_X];
__device__ bf16  g_qkb [SZ_X * 2];        // [8192][1024]: q cols 0-511, k cols 512-1023
__device__ bf16  g_wqkt[1024 * ND];       // [1024][512]  rows 0-511 WqT, 512-1023 WkT
__device__ bf16  g_wvt[(ND * NH) * ND];   // [4096][512] WvT
__device__ bf16  g_wot[ND * (ND * NH)];   // [512][4096] WoT
__device__ bf16  g_vt [SZ_VT];            // [b][4096][1024]  V^T per batch
__device__ bf16  g_ob [SZ_O];             // [8192][4096] attention output
__device__ float g_y  [SZ_X];             // pre-LN (o@Wo + bo + x)

// ---------------------------------------------------------------
__device__ __forceinline__ uint32_t pack_bf16(float lo, float hi) {
    return ((uint32_t)__bfloat16_as_ushort(__float2bfloat16(hi)) << 16) |
            (uint32_t)__bfloat16_as_ushort(__float2bfloat16(lo));
}

__device__ __forceinline__ float ex2f(float x) {
    float r;
    asm("ex2.approx.f32 %0, %1;" : "=f"(r) : "f"(x));
    return r;
}

__device__ __forceinline__ void mma16816(float* d, const uint32_t* a, const uint32_t* b) {
    asm volatile(
        "mma.sync.aligned.m16n8k16.row.col.f32.bf16.bf16.f32 "
        "{%0,%1,%2,%3}, {%4,%5,%6,%7}, {%8,%9}, {%0,%1,%2,%3};\n"
        : "+f"(d[0]), "+f"(d[1]), "+f"(d[2]), "+f"(d[3])
        : "r"(a[0]), "r"(a[1]), "r"(a[2]), "r"(a[3]), "r"(b[0]), "r"(b[1]));
}

// ldmatrix x4: loads 4 8x8 bf16 matrices; per-lane row address in shared.
__device__ __forceinline__ void ldsm_x4(uint32_t& r0, uint32_t& r1, uint32_t& r2, uint32_t& r3,
                                        const void* p) {
    uint32_t a = (uint32_t)__cvta_generic_to_shared(p);
    asm volatile("ldmatrix.sync.aligned.m8n8.x4.shared.b16 {%0,%1,%2,%3}, [%4];"
                 : "=r"(r0), "=r"(r1), "=r"(r2), "=r"(r3) : "r"(a));
}

__device__ __forceinline__ void cpasync16(void* s, const void* g) {
    uint32_t sa = (uint32_t)__cvta_generic_to_shared(s);
    asm volatile("cp.async.cg.shared.global [%0], [%1], 16;\n" :: "r"(sa), "l"(g));
}
__device__ __forceinline__ void cpcommit() { asm volatile("cp.async.commit_group;\n" ::: "memory"); }
__device__ __forceinline__ void cpwait0()  { asm volatile("cp.async.wait_group 0;\n" ::: "memory"); }
__device__ __forceinline__ void cpwait1()  { asm volatile("cp.async.wait_group 1;\n" ::: "memory"); }

// -------- elementwise convert fp32 -> bf16 --------
__global__ void f32_to_bf16_k(const float* __restrict__ in, bf16* __restrict__ out, int n) {
    int i = (blockIdx.x * blockDim.x + threadIdx.x) * 4;
    if (i >= n) return;
    float4 v = *reinterpret_cast<const float4*>(in + i);
    uint2 u;
    u.x = pack_bf16(v.x, v.y);
    u.y = pack_bf16(v.z, v.w);
    *reinterpret_cast<uint2*>(out + i) = u;
}

// -------- transpose + convert: out[c][r] = in[r][c] --------
__global__ void transpose_to_bf16(const float* __restrict__ in, bf16* __restrict__ out,
                                  int R, int C) {
    __shared__ float t[32][33];
    int c0 = blockIdx.x * 32, r0 = blockIdx.y * 32;
    int tx = threadIdx.x;
    for (int i = threadIdx.y; i < 32; i += 8)
        t[i][tx] = in[(size_t)(r0 + i) * C + c0 + tx];
    __syncthreads();
    for (int i = threadIdx.y; i < 32; i += 8)
        out[(size_t)(c0 + i) * R + r0 + tx] = __float2bfloat16(t[tx][i]);
}

// -------- generic batched bf16 GEMM (BK=64, dynamic smem, cp.async 2-stage) --------
// C[m,n] = alpha * sum_k A[m,k] * B[n,k]
// MODE 1: bf16 store     MODE 2: fp32 store + bias[n] + resid[m,n]
#define BM 128
#define BN 128
#define BK 64
#define BKP 72   // padded smem row (bf16), 144B stride -> ldmatrix conflict-free
static constexpr int GEMM_SMEM = 4 * 128 * BKP * 2;   // 2 stages x (A + B) = 73728 B

template <int MODE>
__global__ __launch_bounds__(256)
void gemm_bf16_tn(const bf16* __restrict__ A, const bf16* __restrict__ B,
                  void* __restrict__ Cv,
                  int M, int N, int Kd, int lda, int ldb, int ldc,
                  long long sA1, long long sA2, long long sB1, long long sB2,
                  long long sC1, long long sC2, int Z1,
                  float alpha, const float* __restrict__ bias,
                  const float* __restrict__ resid, int ldres) {
    extern __shared__ __align__(16) bf16 gsm[];
    int z = blockIdx.z;
    int z1 = z % Z1, z2 = z / Z1;
    A += (size_t)z1 * sA1 + (size_t)z2 * sA2;
    B += (size_t)z1 * sB1 + (size_t)z2 * sB2;
    long long coff = (long long)z1 * sC1 + (long long)z2 * sC2;

    int tid  = threadIdx.x;
    int warp = tid >> 5, lane = tid & 31;
    int wm = (warp & 1) * 64;
    int wn = (warp >> 1) * 32;
    int bm0 = blockIdx.y * BM;
    int bn0 = blockIdx.x * BN;

    float acc[4][4][4];
#pragma unroll
    for (int i = 0; i < 4; i++)
#pragma unroll
        for (int j = 0; j < 4; j++)
#pragma unroll
            for (int r = 0; r < 4; r++) acc[i][j][r] = 0.f;

    int rq = lane >> 2;
    int cq = lane & 3;
    int l16 = lane & 15, lhi = (lane >> 4) * 8;
    int ldr = tid >> 3;          // 0..31
    int ldcv = (tid & 7) * 8;    // 0..56

    // stage p: A at gsm + p*2*128*BKP, B at +128*BKP
    auto load_stage = [&](int kt, int p) {
        bf16* Ap = gsm + (size_t)p * 2 * 128 * BKP;
        bf16* Bp = Ap + 128 * BKP;
#pragma unroll
        for (int i = 0; i < 4; i++) {
            int r = ldr + i * 32;
            cpasync16(Ap + r * BKP + ldcv, A + (size_t)(bm0 + r) * lda + kt + ldcv);
            cpasync16(Bp + r * BKP + ldcv, B + (size_t)(bn0 + r) * ldb + kt + ldcv);
        }
    };

    load_stage(0, 0);
    cpcommit();

    int p = 0;
    for (int kt = 0; kt < Kd; kt += BK, p ^= 1) {
        cpwait0();
        __syncthreads();
        if (kt + BK < Kd) {
            load_stage(kt + BK, p ^ 1);
            cpcommit();
        }

        const bf16* As = gsm + (size_t)p * 2 * 128 * BKP;
        const bf16* Bsp = As + 128 * BKP;
#pragma unroll
        for (int ks = 0; ks < 4; ks++) {
            int kk = ks * 16 + lhi;
            uint32_t afr[4][4];
#pragma unroll
            for (int i = 0; i < 4; i++)
                ldsm_x4(afr[i][0], afr[i][1], afr[i][2], afr[i][3],
                        As + (wm + i * 16 + l16) * BKP + kk);
            uint32_t bfr[4][2];
#pragma unroll
            for (int jp = 0; jp < 2; jp++) {
                uint32_t b0, b1, b2, b3;
                ldsm_x4(b0, b1, b2, b3, Bsp + (wn + jp * 16 + l16) * BKP + kk);
                bfr[2 * jp][0] = b0; bfr[2 * jp][1] = b2;
                bfr[2 * jp + 1][0] = b1; bfr[2 * jp + 1][1] = b3;
            }
#pragma unroll
            for (int i = 0; i < 4; i++)
#pragma unroll
                for (int j = 0; j < 4; j++)
                    mma16816(acc[i][j], afr[i], bfr[j]);
        }
        __syncthreads();
    }

    int cq2 = cq * 2;
    float* Cf = (MODE == 1) ? nullptr : (float*)Cv + coff;
    bf16*  Cb = (MODE == 1) ? (bf16*)Cv + coff : nullptr;
#pragma unroll
    for (int i = 0; i < 4; i++) {
#pragma unroll
        for (int j = 0; j < 4; j++) {
            int row = bm0 + wm + i * 16 + rq;
            int col = bn0 + wn + j * 8 + cq2;
            float c0 = acc[i][j][0] * alpha, c1 = acc[i][j][1] * alpha;
            float c2 = acc[i][j][2] * alpha, c3 = acc[i][j][3] * alpha;
            if (MODE == 2) {
                float b0v = bias[col], b1v = bias[col + 1];
                const float* r0p = resid + (size_t)row * ldres + col;
                const float* r1p = resid + (size_t)(row + 8) * ldres + col;
                c0 += b0v + r0p[0]; c1 += b1v + r0p[1];
                c2 += b0v + r1p[0]; c3 += b1v + r1p[1];
            }
            if (MODE == 1) {
                *reinterpret_cast<uint32_t*>(Cb + (size_t)row * ldc + col)       = pack_bf16(c0, c1);
                *reinterpret_cast<uint32_t*>(Cb + (size_t)(row + 8) * ldc + col) = pack_bf16(c2, c3);
            } else {
                *reinterpret_cast<float2*>(Cf + (size_t)row * ldc + col)       = make_float2(c0, c1);
                *reinterpret_cast<float2*>(Cf + (size_t)(row + 8) * ldc + col) = make_float2(c2, c3);
            }
        }
    }
}

// ================================================================
// Fused flash attention (R11/R15-validated). d-chunk = 256;
// exp2-domain softmax; batched exp2 before PV; reduce deferred.
// Block: q-tile 128 x d-chunk 256 for one (b,h); 8 s-iters of 128.
// grid = (16, 64): x = dch*8 + qt (dch 0..1), y = b*8 + h.
// Smem: Q[128*72] | K[2][128*72] | V[2][256*136]   (~190 KB)
// ================================================================
#define SCALE_LOG2 0.18033688f   // 0.125 * log2(e)
static constexpr int FQS = 72;    // Q/K row stride bf16 (144B, conflict-free)
static constexpr int FVS = 136;   // V row stride bf16 (272B, conflict-free)
static constexpr int FLASH_SMEM = (128 * FQS * 3 + 2 * 256 * FVS) * 2;

__global__ __launch_bounds__(256, 1)
void flash_attn_k(const bf16* __restrict__ QKg, const bf16* __restrict__ Vg,
                  bf16* __restrict__ Og) {
    extern __shared__ __align__(16) char fsm[];
    bf16* Qs = (bf16*)fsm;           // 128*72
    bf16* Ks = Qs + 128 * FQS;       // 2 bufs of 128*72
    bf16* Vs = Ks + 2 * 128 * FQS;   // 2 bufs of 256*136

    int tid  = threadIdx.x;
    int warp = tid >> 5, lane = tid & 31;
    int rq = lane >> 2, cq = lane & 3, cq2 = cq << 1;
    int l16 = lane & 15, lhi = (lane >> 4) * 8;
    int w16 = warp * 16;
    int qt = blockIdx.x & 7, dch = blockIdx.x >> 3;   // dch 0..1
    int b  = blockIdx.y >> 3, h = blockIdx.y & 7;

    const bf16* Qp = QKg + ((size_t)(b * 1024 + qt * 128)) * 1024 + h * 64;
    const bf16* Kp = QKg + ((size_t)(b * 1024)) * 1024 + 512 + h * 64;
    const bf16* Vp = Vg + (size_t)b * 4194304 + ((size_t)(h * 512 + dch * 256)) * 1024;

#pragma unroll
    for (int p = 0; p < 4; p++) {
        int idx = tid + p * 256; int r = idx >> 3, c = (idx & 7) * 8;
        cpasync16(Qs + r * FQS + c, Qp + (size_t)r * 1024 + c);
    }
    cpcommit();
#pragma unroll
    for (int p = 0; p < 4; p++) {
        int idx = tid + p * 256; int r = idx >> 3, c = (idx & 7) * 8;
        cpasync16(Ks + r * FQS + c, Kp + (size_t)r * 1024 + c);
    }
#pragma unroll
    for (int p = 0; p < 16; p++) {
        int idx = tid + p * 256; int r = idx >> 4, c = (idx & 15) * 8;
        cpasync16(Vs + r * FVS + c, Vp + (size_t)r * 1024 + c);
    }
    cpcommit();

    cpwait1();
    __syncthreads();
    uint32_t qfr[4][4];
#pragma unroll
    for (int kg = 0; kg < 4; kg++)
        ldsm_x4(qfr[kg][0], qfr[kg][1], qfr[kg][2], qfr[kg][3],
                Qs + (w16 + l16) * FQS + kg * 16 + lhi);

    float oacc[32][4];
#pragma unroll
    for (int n = 0; n < 32; n++)
#pragma unroll
        for (int r = 0; r < 4; r++) oacc[n][r] = 0.f;
    float m0 = -1e30f, m1 = -1e30f, l0 = 0.f, l1 = 0.f;

    int cur = 0;
    for (int st = 0; st < 8; st++) {
        cpwait0();
        __syncthreads();
        if (st < 7) {
            int nb = cur ^ 1;
            int s1 = (st + 1) * 128;
#pragma unroll
            for (int p = 0; p < 4; p++) {
                int idx = tid + p * 256; int r = idx >> 3, c = (idx & 7) * 8;
                cpasync16(Ks + nb * 128 * FQS + r * FQS + c, Kp + (size_t)(s1 + r) * 1024 + c);
            }
#pragma unroll
            for (int p = 0; p < 16; p++) {
                int idx = tid + p * 256; int r = idx >> 4, c = (idx & 15) * 8;
                cpasync16(Vs + nb * 256 * FVS + r * FVS + c, Vp + (size_t)r * 1024 + s1 + c);
            }
            cpcommit();
        }

        // ---- S = Q·K^T : M=16 (warp rows), N=128, K=64 ----
        float sacc[16][4];
#pragma unroll
        for (int j = 0; j < 16; j++)
#pragma unroll
            for (int r = 0; r < 4; r++) sacc[j][r] = 0.f;

        const bf16* Kc = Ks + cur * 128 * FQS;
#pragma unroll
        for (int kg = 0; kg < 4; kg++) {
#pragma unroll
            for (int jp = 0; jp < 8; jp++) {
                uint32_t b0, b1, b2, b3;
                ldsm_x4(b0, b1, b2, b3, Kc + (jp * 16 + l16) * FQS + kg * 16 + lhi);
                uint32_t bfA[2] = {b0, b2}, bfB[2] = {b1, b3};
                mma16816(sacc[2 * jp],     qfr[kg], bfA);
                mma16816(sacc[2 * jp + 1], qfr[kg], bfB);
            }
        }

        // mask (raw==0) + scale into log2 domain (0.125*log2e)
#pragma unroll
        for (int j = 0; j < 16; j++)
#pragma unroll
            for (int r = 0; r < 4; r++) {
                float v = sacc[j][r];
                sacc[j][r] = (v == 0.f) ? -1e9f : v * SCALE_LOG2;
            }

        // ---- row max (quad shuffle only) ----
        float mx0 = -1e30f, mx1 = -1e30f;
#pragma unroll
        for (int j = 0; j < 16; j++) {
            mx0 = fmaxf(mx0, fmaxf(sacc[j][0], sacc[j][1]));
            mx1 = fmaxf(mx1, fmaxf(sacc[j][2], sacc[j][3]));
        }
        mx0 = fmaxf(mx0, __shfl_xor_sync(0xffffffffu, mx0, 1));
        mx0 = fmaxf(mx0, __shfl_xor_sync(0xffffffffu, mx0, 2));
        mx1 = fmaxf(mx1, __shfl_xor_sync(0xffffffffu, mx1, 1));
        mx1 = fmaxf(mx1, __shfl_xor_sync(0xffffffffu, mx1, 2));

        float nm0 = fmaxf(m0, mx0), nm1 = fmaxf(m1, mx1);
        float scf0 = ex2f(m0 - nm0), scf1 = ex2f(m1 - nm1);
        m0 = nm0; m1 = nm1;

#pragma unroll
        for (int n = 0; n < 32; n++) {
            oacc[n][0] *= scf0; oacc[n][1] *= scf0;
            oacc[n][2] *= scf1; oacc[n][3] *= scf1;
        }

        // ---- P = exp2(S' - m') in registers (batched; reduce deferred) ----
        uint32_t pf[8][4];
        float rs0 = 0.f, rs1 = 0.f;
#pragma unroll
        for (int kg = 0; kg < 8; kg++) {
            int j0 = 2 * kg, j1 = 2 * kg + 1;
            float e00 = ex2f(sacc[j0][0] - m0), e01 = ex2f(sacc[j0][1] - m0);
            float e02 = ex2f(sacc[j0][2] - m1), e03 = ex2f(sacc[j0][3] - m1);
            float e10 = ex2f(sacc[j1][0] - m0), e11 = ex2f(sacc[j1][1] - m0);
            float e12 = ex2f(sacc[j1][2] - m1), e13 = ex2f(sacc[j1][3] - m1);
            rs0 += e00 + e01 + e10 + e11;
            rs1 += e02 + e03 + e12 + e13;
            pf[kg][0] = pack_bf16(e00, e01);
            pf[kg][1] = pack_bf16(e02, e03);
            pf[kg][2] = pack_bf16(e10, e11);
            pf[kg][3] = pack_bf16(e12, e13);
        }

        // ---- O += P·V : M=16, N=256 (d), K=128 (s) ----
        const bf16* Vc = Vs + cur * 256 * FVS;
#pragma unroll
        for (int kg = 0; kg < 8; kg++) {
#pragma unroll
            for (int np = 0; np < 16; np++) {
                uint32_t b0, b1, b2, b3;
                ldsm_x4(b0, b1, b2, b3, Vc + (np * 16 + l16) * FVS + kg * 16 + lhi);
                uint32_t bfA[2] = {b0, b2}, bfB[2] = {b1, b3};
                mma16816(oacc[2 * np],     pf[kg], bfA);
                mma16816(oacc[2 * np + 1], pf[kg], bfB);
            }
        }

        // deferred rowsum reduce + l update (shadowed by PV mma drain)
        rs0 += __shfl_xor_sync(0xffffffffu, rs0, 1);
        rs0 += __shfl_xor_sync(0xffffffffu, rs0, 2);
        rs1 += __shfl_xor_sync(0xffffffffu, rs1, 1);
        rs1 += __shfl_xor_sync(0xffffffffu, rs1, 2);
        l0 = l0 * scf0 + rs0;
        l1 = l1 * scf1 + rs1;

        cur ^= 1;
    }

    // ---- epilogue: O / l -> ob (bf16) ----
    float inv0 = 1.f / l0, inv1 = 1.f / l1;
    int row = b * 1024 + qt * 128 + w16 + rq;
    int colb = h * 512 + dch * 256 + cq2;
#pragma unroll
    for (int n = 0; n < 32; n++) {
        int col = colb + n * 8;
        *reinterpret_cast<uint32_t*>(Og + (size_t)row * 4096 + col) =
            pack_bf16(oacc[n][0] * inv0, oacc[n][1] * inv0);
        *reinterpret_cast<uint32_t*>(Og + (size_t)(row + 8) * 4096 + col) =
            pack_bf16(oacc[n][2] * inv1, oacc[n][3] * inv1);
    }
}

// -------- LayerNorm over D=512, eps=1e-6 --------
__global__ void layernorm_k(const float* __restrict__ y, const float* __restrict__ gamma,
                            const float* __restrict__ beta, float* __restrict__ out) {
    int row = blockIdx.x;
    int t = threadIdx.x;
    const float4* p = reinterpret_cast<const float4*>(y + (size_t)row * 512);
    float4 v = p[t];
    float s = v.x + v.y + v.z + v.w;
#pragma unroll
    for (int o = 16; o; o >>= 1) s += __shfl_xor_sync(0xffffffffu, s, o);
    __shared__ float sm[4];
    if ((t & 31) == 0) sm[t >> 5] = s;
    __syncthreads();
    float mu = (sm[0] + sm[1] + sm[2] + sm[3]) * (1.0f / 512.0f);
    float dx = v.x - mu, dy = v.y - mu, dz = v.z - mu, dw = v.w - mu;
    float q = dx * dx + dy * dy + dz * dz + dw * dw;
#pragma unroll
    for (int o = 16; o; o >>= 1) q += __shfl_xor_sync(0xffffffffu, q, o);
    __shared__ float sq[4];
    if ((t & 31) == 0) sq[t >> 5] = q;
    __syncthreads();
    float var = (sq[0] + sq[1] + sq[2] + sq[3]) * (1.0f / 512.0f);
    float rs = rsqrtf(var + 1e-6f);
    float4 g = reinterpret_cast<const float4*>(gamma)[t];
    float4 b = reinterpret_cast<const float4*>(beta)[t];
    float4 r;
    r.x = dx * rs * g.x + b.x;
    r.y = dy * rs * g.y + b.y;
    r.z = dz * rs * g.z + b.z;
    r.w = dw * rs * g.w + b.w;
    reinterpret_cast<float4*>(out + (size_t)row * 512)[t] = r;
}

// ---------------------------------------------------------------
extern "C" void kernel_launch(void* const* d_in, const int* in_sizes, int n_in,
                              void* d_out, int out_size) {
    const float* x     = (const float*)d_in[0];
    const float* Wq    = (const float*)d_in[1];
    const float* Wk    = (const float*)d_in[2];
    const float* Wv    = (const float*)d_in[3];
    const float* Wo    = (const float*)d_in[4];
    const float* bo    = (const float*)d_in[5];
    const float* gamma = (const float*)d_in[6];
    const float* beta  = (const float*)d_in[7];
    float* out = (float*)d_out;

    bf16 *xb, *qkb, *wqkt, *wvt, *wot, *vt, *ob;
    float *yb;
    cudaGetSymbolAddress((void**)&xb,   g_xb);
    cudaGetSymbolAddress((void**)&qkb,  g_qkb);
    cudaGetSymbolAddress((void**)&wqkt, g_wqkt);
    cudaGetSymbolAddress((void**)&wvt,  g_wvt);
    cudaGetSymbolAddress((void**)&wot,  g_wot);
    cudaGetSymbolAddress((void**)&vt,   g_vt);
    cudaGetSymbolAddress((void**)&ob,   g_ob);
    cudaGetSymbolAddress((void**)&yb,   g_y);

    cudaFuncSetAttribute(flash_attn_k, cudaFuncAttributeMaxDynamicSharedMemorySize, FLASH_SMEM);
    cudaFuncSetAttribute(gemm_bf16_tn<1>, cudaFuncAttributeMaxDynamicSharedMemorySize, GEMM_SMEM);
    cudaFuncSetAttribute(gemm_bf16_tn<2>, cudaFuncAttributeMaxDynamicSharedMemorySize, GEMM_SMEM);

    // 1) x -> bf16
    f32_to_bf16_k<<<(int)(SZ_X / 4 / 256), 256>>>(x, xb, (int)SZ_X);
    // 2) transposed bf16 weights (Wq and Wk into one concatenated buffer)
    transpose_to_bf16<<<dim3(16, 16),  dim3(32, 8)>>>(Wq, wqkt, 512, 512);
    transpose_to_bf16<<<dim3(16, 16),  dim3(32, 8)>>>(Wk, wqkt + 512 * 512, 512, 512);
    transpose_to_bf16<<<dim3(128, 16), dim3(32, 8)>>>(Wv, wvt, 512, 4096);
    transpose_to_bf16<<<dim3(16, 128), dim3(32, 8)>>>(Wo, wot, 4096, 512);

    // 3) [q|k] = x @ [Wq|Wk]   [8192,1024]
    gemm_bf16_tn<1><<<dim3(8, 64, 1), 256, GEMM_SMEM>>>(xb, wqkt, qkb, 8192, 1024, 512,
        512, 512, 1024, 0, 0, 0, 0, 0, 0, 1, 1.0f, nullptr, nullptr, 0);
    // 4) Vt[b] = WvT @ x[b]^T  -> [b][4096][1024]
    gemm_bf16_tn<1><<<dim3(8, 32, 8), 256, GEMM_SMEM>>>(wvt, xb, vt, 4096, 1024, 512,
        512, 512, 1024, 0, 0, 0, 524288LL, 0, 4194304LL, 1, 1.0f, nullptr, nullptr, 0);
    // 5) fused attention: scores + mask + softmax + P·V -> ob  (d-chunk 256)
    flash_attn_k<<<dim3(16, 64), 256, FLASH_SMEM>>>(qkb, vt, ob);
    // 6) y = o @ Wo + bo + x
    gemm_bf16_tn<2><<<dim3(4, 64, 1), 256, GEMM_SMEM>>>(ob, wot, yb, 8192, 512, 4096,
        4096, 4096, 512, 0, 0, 0, 0, 0, 0, 1, 1.0f, bo, x, 512);
    // 7) LayerNorm -> out
    layernorm_k<<<8192, 128>>>(yb, gamma, beta, out);
}

// round 17
// speedup vs baseline: 1.1415x; 1.0291x over previous
#include <cuda_runtime.h>
#include <cuda_bf16.h>
#include <cstdint>

using bf16 = __nv_bfloat16;

// Problem dims
static constexpr int NB = 8, NS = 1024, ND = 512, NK = 64, NH = 8;

static constexpr size_t SZ_X  = (size_t)NB * NS * ND;          // 4,194,304
static constexpr size_t SZ_VT = (size_t)NB * (ND * NH) * NS;   // 33,554,432
static constexpr size_t SZ_O  = (size_t)NB * NS * (NH * ND);   // 33,554,432

// -------- static scratch (no runtime allocation allowed) --------
__device__ bf16  g_xb  [SZ_X];
__device__ bf16  g_qkb [SZ_X * 2];        // [8192][1024]: q cols 0-511, k cols 512-1023
__device__ bf16  g_wqkt[1024 * ND];       // [1024][512]  rows 0-511 WqT, 512-1023 WkT
__device__ bf16  g_wvt[(ND * NH) * ND];   // [4096][512] WvT
__device__ bf16  g_wot[ND * (ND * NH)];   // [512][4096] WoT
__device__ bf16  g_vt [SZ_VT];            // [b][4096][1024]  V^T per batch
__device__ bf16  g_ob [SZ_O];             // [8192][4096] attention output
__device__ float g_y  [SZ_X];             // pre-LN (o@Wo + bo + x)

// ---------------------------------------------------------------
__device__ __forceinline__ uint32_t pack_bf16(float lo, float hi) {
    return ((uint32_t)__bfloat16_as_ushort(__float2bfloat16(hi)) << 16) |
            (uint32_t)__bfloat16_as_ushort(__float2bfloat16(lo));
}

__device__ __forceinline__ float ex2f(float x) {
    float r;
    asm("ex2.approx.f32 %0, %1;" : "=f"(r) : "f"(x));
    return r;
}

__device__ __forceinline__ void mma16816(float* d, const uint32_t* a, const uint32_t* b) {
    asm volatile(
        "mma.sync.aligned.m16n8k16.row.col.f32.bf16.bf16.f32 "
        "{%0,%1,%2,%3}, {%4,%5,%6,%7}, {%8,%9}, {%0,%1,%2,%3};\n"
        : "+f"(d[0]), "+f"(d[1]), "+f"(d[2]), "+f"(d[3])
        : "r"(a[0]), "r"(a[1]), "r"(a[2]), "r"(a[3]), "r"(b[0]), "r"(b[1]));
}

// ldmatrix x4: loads 4 8x8 bf16 matrices; per-lane row address in shared.
__device__ __forceinline__ void ldsm_x4(uint32_t& r0, uint32_t& r1, uint32_t& r2, uint32_t& r3,
                                        const void* p) {
    uint32_t a = (uint32_t)__cvta_generic_to_shared(p);
    asm volatile("ldmatrix.sync.aligned.m8n8.x4.shared.b16 {%0,%1,%2,%3}, [%4];"
                 : "=r"(r0), "=r"(r1), "=r"(r2), "=r"(r3) : "r"(a));
}

__device__ __forceinline__ void cpasync16(void* s, const void* g) {
    uint32_t sa = (uint32_t)__cvta_generic_to_shared(s);
    asm volatile("cp.async.cg.shared.global [%0], [%1], 16;\n" :: "r"(sa), "l"(g));
}
__device__ __forceinline__ void cpcommit() { asm volatile("cp.async.commit_group;\n" ::: "memory"); }
__device__ __forceinline__ void cpwait0()  { asm volatile("cp.async.wait_group 0;\n" ::: "memory"); }
__device__ __forceinline__ void cpwait1()  { asm volatile("cp.async.wait_group 1;\n" ::: "memory"); }

// ================================================================
// Fused prep: x->bf16 convert + all 4 weight transposes, one launch.
// Blocks [0,4096): convert (1024 elems each).
// [4096,4352): Wq-T   [4352,4608): Wk-T
// [4608,6656): Wv-T (128x16 tiles)   [6656,8704): Wo-T (16x128 tiles)
// ================================================================
__global__ __launch_bounds__(256)
void prep_k(const float* __restrict__ x, bf16* __restrict__ xb,
            const float* __restrict__ Wq, const float* __restrict__ Wk,
            const float* __restrict__ Wv, const float* __restrict__ Wo,
            bf16* __restrict__ wqkt, bf16* __restrict__ wvt, bf16* __restrict__ wot) {
    int blk = blockIdx.x;
    int tid = threadIdx.x;
    if (blk < 4096) {
        int i = (blk * 256 + tid) * 4;
        float4 v = *reinterpret_cast<const float4*>(x + i);
        uint2 u;
        u.x = pack_bf16(v.x, v.y);
        u.y = pack_bf16(v.z, v.w);
        *reinterpret_cast<uint2*>(xb + i) = u;
        return;
    }
    __shared__ float t[32][33];
    const float* in; bf16* out; int R, C, bx, by;
    if (blk < 4352)      { int l = blk - 4096; in = Wq; out = wqkt;          R = 512;  C = 512;  bx = l & 15;  by = l >> 4; }
    else if (blk < 4608) { int l = blk - 4352; in = Wk; out = wqkt + 262144; R = 512;  C = 512;  bx = l & 15;  by = l >> 4; }
    else if (blk < 6656) { int l = blk - 4608; in = Wv; out = wvt;           R = 512;  C = 4096; bx = l & 127; by = l >> 7; }
    else                 { int l = blk - 6656; in = Wo; out = wot;           R = 4096; C = 512;  bx = l & 15;  by = l >> 4; }
    int tx = tid & 31, ty = tid >> 5;
    int c0 = bx * 32, r0 = by * 32;
    for (int i = ty; i < 32; i += 8)
        t[i][tx] = in[(size_t)(r0 + i) * C + c0 + tx];
    __syncthreads();
    for (int i = ty; i < 32; i += 8)
        out[(size_t)(c0 + i) * R + r0 + tx] = __float2bfloat16(t[tx][i]);
}

// -------- GEMM core (BK=64, dynamic smem, cp.async 2-stage) — R16-validated body --------
// C[m,n] = alpha * sum_k A[m,k] * B[n,k]
// MODE 1: bf16 store     MODE 2: fp32 store + bias[n] + resid[m,n]
#define BM 128
#define BN 128
#define BK 64
#define BKP 72   // padded smem row (bf16), 144B stride -> ldmatrix conflict-free
static constexpr int GEMM_SMEM = 4 * 128 * BKP * 2;   // 2 stages x (A + B) = 73728 B

template <int MODE>
__device__ __forceinline__
void gemm_core(const bf16* __restrict__ A, const bf16* __restrict__ B,
               void* __restrict__ Cv, long long coff,
               int lda, int ldb, int ldc, int Kd,
               int bm0, int bn0, float alpha,
               const float* __restrict__ bias, const float* __restrict__ resid, int ldres,
               bf16* gsm) {
    int tid  = threadIdx.x;
    int warp = tid >> 5, lane = tid & 31;
    int wm = (warp & 1) * 64;
    int wn = (warp >> 1) * 32;

    float acc[4][4][4];
#pragma unroll
    for (int i = 0; i < 4; i++)
#pragma unroll
        for (int j = 0; j < 4; j++)
#pragma unroll
            for (int r = 0; r < 4; r++) acc[i][j][r] = 0.f;

    int rq = lane >> 2;
    int cq = lane & 3;
    int l16 = lane & 15, lhi = (lane >> 4) * 8;
    int ldr = tid >> 3;          // 0..31
    int ldcv = (tid & 7) * 8;    // 0..56

    auto load_stage = [&](int kt, int p) {
        bf16* Ap = gsm + (size_t)p * 2 * 128 * BKP;
        bf16* Bp = Ap + 128 * BKP;
#pragma unroll
        for (int i = 0; i < 4; i++) {
            int r = ldr + i * 32;
            cpasync16(Ap + r * BKP + ldcv, A + (size_t)(bm0 + r) * lda + kt + ldcv);
            cpasync16(Bp + r * BKP + ldcv, B + (size_t)(bn0 + r) * ldb + kt + ldcv);
        }
    };

    load_stage(0, 0);
    cpcommit();

    int p = 0;
    for (int kt = 0; kt < Kd; kt += BK, p ^= 1) {
        cpwait0();
        __syncthreads();
        if (kt + BK < Kd) {
            load_stage(kt + BK, p ^ 1);
            cpcommit();
        }

        const bf16* As = gsm + (size_t)p * 2 * 128 * BKP;
        const bf16* Bsp = As + 128 * BKP;
#pragma unroll
        for (int ks = 0; ks < 4; ks++) {
            int kk = ks * 16 + lhi;
            uint32_t afr[4][4];
#pragma unroll
            for (int i = 0; i < 4; i++)
                ldsm_x4(afr[i][0], afr[i][1], afr[i][2], afr[i][3],
                        As + (wm + i * 16 + l16) * BKP + kk);
            uint32_t bfr[4][2];
#pragma unroll
            for (int jp = 0; jp < 2; jp++) {
                uint32_t b0, b1, b2, b3;
                ldsm_x4(b0, b1, b2, b3, Bsp + (wn + jp * 16 + l16) * BKP + kk);
                bfr[2 * jp][0] = b0; bfr[2 * jp][1] = b2;
                bfr[2 * jp + 1][0] = b1; bfr[2 * jp + 1][1] = b3;
            }
#pragma unroll
            for (int i = 0; i < 4; i++)
#pragma unroll
                for (int j = 0; j < 4; j++)
                    mma16816(acc[i][j], afr[i], bfr[j]);
        }
        __syncthreads();
    }

    int cq2 = cq * 2;
    float* Cf = (MODE == 1) ? nullptr : (float*)Cv + coff;
    bf16*  Cb = (MODE == 1) ? (bf16*)Cv + coff : nullptr;
#pragma unroll
    for (int i = 0; i < 4; i++) {
#pragma unroll
        for (int j = 0; j < 4; j++) {
            int row = bm0 + wm + i * 16 + rq;
            int col = bn0 + wn + j * 8 + cq2;
            float c0 = acc[i][j][0] * alpha, c1 = acc[i][j][1] * alpha;
            float c2 = acc[i][j][2] * alpha, c3 = acc[i][j][3] * alpha;
            if (MODE == 2) {
                float b0v = bias[col], b1v = bias[col + 1];
                const float* r0p = resid + (size_t)row * ldres + col;
                const float* r1p = resid + (size_t)(row + 8) * ldres + col;
                c0 += b0v + r0p[0]; c1 += b1v + r0p[1];
                c2 += b0v + r1p[0]; c3 += b1v + r1p[1];
            }
            if (MODE == 1) {
                *reinterpret_cast<uint32_t*>(Cb + (size_t)row * ldc + col)       = pack_bf16(c0, c1);
                *reinterpret_cast<uint32_t*>(Cb + (size_t)(row + 8) * ldc + col) = pack_bf16(c2, c3);
            } else {
                *reinterpret_cast<float2*>(Cf + (size_t)row * ldc + col)       = make_float2(c0, c1);
                *reinterpret_cast<float2*>(Cf + (size_t)(row + 8) * ldc + col) = make_float2(c2, c3);
            }
        }
    }
}

// Fused qk-projection + Vt GEMM: grid (8, 64, 9).
// z == 0: [q|k] = x @ [Wq|Wk]  (M=8192, N=1024, K=512)
// z >= 1: Vt[b=z-1] = WvT @ x[b]^T (M=4096 -> y<32 only, N=1024, K=512)
__global__ __launch_bounds__(256)
void gemm_qkvt(const bf16* __restrict__ xb, const bf16* __restrict__ wqkt,
               bf16* __restrict__ qkb, const bf16* __restrict__ wvt,
               bf16* __restrict__ vt) {
    extern __shared__ __align__(16) bf16 gsm[];
    int z = blockIdx.z;
    if (z == 0) {
        gemm_core<1>(xb, wqkt, qkb, 0, 512, 512, 1024, 512,
                     blockIdx.y * 128, blockIdx.x * 128, 1.0f, nullptr, nullptr, 0, gsm);
    } else {
        if (blockIdx.y >= 32) return;
        int b = z - 1;
        gemm_core<1>(wvt, xb + (size_t)b * 524288, vt, (long long)b * 4194304LL,
                     512, 512, 1024, 512,
                     blockIdx.y * 128, blockIdx.x * 128, 1.0f, nullptr, nullptr, 0, gsm);
    }
}

// Wo GEMM wrapper (MODE 2), unchanged semantics from R16.
__global__ __launch_bounds__(256)
void gemm_wo(const bf16* __restrict__ ob, const bf16* __restrict__ wot,
             float* __restrict__ yb, const float* __restrict__ bias,
             const float* __restrict__ resid) {
    extern __shared__ __align__(16) bf16 gsm[];
    gemm_core<2>(ob, wot, yb, 0, 4096, 4096, 512, 4096,
                 blockIdx.y * 128, blockIdx.x * 128, 1.0f, bias, resid, 512, gsm);
}

// ================================================================
// Fused flash attention (R11/R15-validated). d-chunk = 256;
// exp2-domain softmax; batched exp2 before PV; reduce deferred.
// Block: q-tile 128 x d-chunk 256 for one (b,h); 8 s-iters of 128.
// grid = (16, 64): x = dch*8 + qt (dch 0..1), y = b*8 + h.
// Smem: Q[128*72] | K[2][128*72] | V[2][256*136]   (~190 KB)
// ================================================================
#define SCALE_LOG2 0.18033688f   // 0.125 * log2(e)
static constexpr int FQS = 72;    // Q/K row stride bf16 (144B, conflict-free)
static constexpr int FVS = 136;   // V row stride bf16 (272B, conflict-free)
static constexpr int FLASH_SMEM = (128 * FQS * 3 + 2 * 256 * FVS) * 2;

__global__ __launch_bounds__(256, 1)
void flash_attn_k(const bf16* __restrict__ QKg, const bf16* __restrict__ Vg,
                  bf16* __restrict__ Og) {
    extern __shared__ __align__(16) char fsm[];
    bf16* Qs = (bf16*)fsm;           // 128*72
    bf16* Ks = Qs + 128 * FQS;       // 2 bufs of 128*72
    bf16* Vs = Ks + 2 * 128 * FQS;   // 2 bufs of 256*136

    int tid  = threadIdx.x;
    int warp = tid >> 5, lane = tid & 31;
    int rq = lane >> 2, cq = lane & 3, cq2 = cq << 1;
    int l16 = lane & 15, lhi = (lane >> 4) * 8;
    int w16 = warp * 16;
    int qt = blockIdx.x & 7, dch = blockIdx.x >> 3;   // dch 0..1
    int b  = blockIdx.y >> 3, h = blockIdx.y & 7;

    const bf16* Qp = QKg + ((size_t)(b * 1024 + qt * 128)) * 1024 + h * 64;
    const bf16* Kp = QKg + ((size_t)(b * 1024)) * 1024 + 512 + h * 64;
    const bf16* Vp = Vg + (size_t)b * 4194304 + ((size_t)(h * 512 + dch * 256)) * 1024;

#pragma unroll
    for (int p = 0; p < 4; p++) {
        int idx = tid + p * 256; int r = idx >> 3, c = (idx & 7) * 8;
        cpasync16(Qs + r * FQS + c, Qp + (size_t)r * 1024 + c);
    }
    cpcommit();
#pragma unroll
    for (int p = 0; p < 4; p++) {
        int idx = tid + p * 256; int r = idx >> 3, c = (idx & 7) * 8;
        cpasync16(Ks + r * FQS + c, Kp + (size_t)r * 1024 + c);
    }
#pragma unroll
    for (int p = 0; p < 16; p++) {
        int idx = tid + p * 256; int r = idx >> 4, c = (idx & 15) * 8;
        cpasync16(Vs + r * FVS + c, Vp + (size_t)r * 1024 + c);
    }
    cpcommit();

    cpwait1();
    __syncthreads();
    uint32_t qfr[4][4];
#pragma unroll
    for (int kg = 0; kg < 4; kg++)
        ldsm_x4(qfr[kg][0], qfr[kg][1], qfr[kg][2], qfr[kg][3],
                Qs + (w16 + l16) * FQS + kg * 16 + lhi);

    float oacc[32][4];
#pragma unroll
    for (int n = 0; n < 32; n++)
#pragma unroll
        for (int r = 0; r < 4; r++) oacc[n][r] = 0.f;
    float m0 = -1e30f, m1 = -1e30f, l0 = 0.f, l1 = 0.f;

    int cur = 0;
    for (int st = 0; st < 8; st++) {
        cpwait0();
        __syncthreads();
        if (st < 7) {
            int nb = cur ^ 1;
            int s1 = (st + 1) * 128;
#pragma unroll
            for (int p = 0; p < 4; p++) {
                int idx = tid + p * 256; int r = idx >> 3, c = (idx & 7) * 8;
                cpasync16(Ks + nb * 128 * FQS + r * FQS + c, Kp + (size_t)(s1 + r) * 1024 + c);
            }
#pragma unroll
            for (int p = 0; p < 16; p++) {
                int idx = tid + p * 256; int r = idx >> 4, c = (idx & 15) * 8;
                cpasync16(Vs + nb * 256 * FVS + r * FVS + c, Vp + (size_t)r * 1024 + s1 + c);
            }
            cpcommit();
        }

        // ---- S = Q·K^T : M=16 (warp rows), N=128, K=64 ----
        float sacc[16][4];
#pragma unroll
        for (int j = 0; j < 16; j++)
#pragma unroll
            for (int r = 0; r < 4; r++) sacc[j][r] = 0.f;

        const bf16* Kc = Ks + cur * 128 * FQS;
#pragma unroll
        for (int kg = 0; kg < 4; kg++) {
#pragma unroll
            for (int jp = 0; jp < 8; jp++) {
                uint32_t b0, b1, b2, b3;
                ldsm_x4(b0, b1, b2, b3, Kc + (jp * 16 + l16) * FQS + kg * 16 + lhi);
                uint32_t bfA[2] = {b0, b2}, bfB[2] = {b1, b3};
                mma16816(sacc[2 * jp],     qfr[kg], bfA);
                mma16816(sacc[2 * jp + 1], qfr[kg], bfB);
            }
        }

        // mask (raw==0) + scale into log2 domain (0.125*log2e)
#pragma unroll
        for (int j = 0; j < 16; j++)
#pragma unroll
            for (int r = 0; r < 4; r++) {
                float v = sacc[j][r];
                sacc[j][r] = (v == 0.f) ? -1e9f : v * SCALE_LOG2;
            }

        // ---- row max (quad shuffle only) ----
        float mx0 = -1e30f, mx1 = -1e30f;
#pragma unroll
        for (int j = 0; j < 16; j++) {
            mx0 = fmaxf(mx0, fmaxf(sacc[j][0], sacc[j][1]));
            mx1 = fmaxf(mx1, fmaxf(sacc[j][2], sacc[j][3]));
        }
        mx0 = fmaxf(mx0, __shfl_xor_sync(0xffffffffu, mx0, 1));
        mx0 = fmaxf(mx0, __shfl_xor_sync(0xffffffffu, mx0, 2));
        mx1 = fmaxf(mx1, __shfl_xor_sync(0xffffffffu, mx1, 1));
        mx1 = fmaxf(mx1, __shfl_xor_sync(0xffffffffu, mx1, 2));

        float nm0 = fmaxf(m0, mx0), nm1 = fmaxf(m1, mx1);
        float scf0 = ex2f(m0 - nm0), scf1 = ex2f(m1 - nm1);
        m0 = nm0; m1 = nm1;

#pragma unroll
        for (int n = 0; n < 32; n++) {
            oacc[n][0] *= scf0; oacc[n][1] *= scf0;
            oacc[n][2] *= scf1; oacc[n][3] *= scf1;
        }

        // ---- P = exp2(S' - m') in registers (batched; reduce deferred) ----
        uint32_t pf[8][4];
        float rs0 = 0.f, rs1 = 0.f;
#pragma unroll
        for (int kg = 0; kg < 8; kg++) {
            int j0 = 2 * kg, j1 = 2 * kg + 1;
            float e00 = ex2f(sacc[j0][0] - m0), e01 = ex2f(sacc[j0][1] - m0);
            float e02 = ex2f(sacc[j0][2] - m1), e03 = ex2f(sacc[j0][3] - m1);
            float e10 = ex2f(sacc[j1][0] - m0), e11 = ex2f(sacc[j1][1] - m0);
            float e12 = ex2f(sacc[j1][2] - m1), e13 = ex2f(sacc[j1][3] - m1);
            rs0 += e00 + e01 + e10 + e11;
            rs1 += e02 + e03 + e12 + e13;
            pf[kg][0] = pack_bf16(e00, e01);
            pf[kg][1] = pack_bf16(e02, e03);
            pf[kg][2] = pack_bf16(e10, e11);
            pf[kg][3] = pack_bf16(e12, e13);
        }

        // ---- O += P·V : M=16, N=256 (d), K=128 (s) ----
        const bf16* Vc = Vs + cur * 256 * FVS;
#pragma unroll
        for (int kg = 0; kg < 8; kg++) {
#pragma unroll
            for (int np = 0; np < 16; np++) {
                uint32_t b0, b1, b2, b3;
                ldsm_x4(b0, b1, b2, b3, Vc + (np * 16 + l16) * FVS + kg * 16 + lhi);
                uint32_t bfA[2] = {b0, b2}, bfB[2] = {b1, b3};
                mma16816(oacc[2 * np],     pf[kg], bfA);
                mma16816(oacc[2 * np + 1], pf[kg], bfB);
            }
        }

        // deferred rowsum reduce + l update (shadowed by PV mma drain)
        rs0 += __shfl_xor_sync(0xffffffffu, rs0, 1);
        rs0 += __shfl_xor_sync(0xffffffffu, rs0, 2);
        rs1 += __shfl_xor_sync(0xffffffffu, rs1, 1);
        rs1 += __shfl_xor_sync(0xffffffffu, rs1, 2);
        l0 = l0 * scf0 + rs0;
        l1 = l1 * scf1 + rs1;

        cur ^= 1;
    }

    // ---- epilogue: O / l -> ob (bf16) ----
    float inv0 = 1.f / l0, inv1 = 1.f / l1;
    int row = b * 1024 + qt * 128 + w16 + rq;
    int colb = h * 512 + dch * 256 + cq2;
#pragma unroll
    for (int n = 0; n < 32; n++) {
        int col = colb + n * 8;
        *reinterpret_cast<uint32_t*>(Og + (size_t)row * 4096 + col) =
            pack_bf16(oacc[n][0] * inv0, oacc[n][1] * inv0);
        *reinterpret_cast<uint32_t*>(Og + (size_t)(row + 8) * 4096 + col) =
            pack_bf16(oacc[n][2] * inv1, oacc[n][3] * inv1);
    }
}

// -------- LayerNorm over D=512, eps=1e-6 --------
__global__ void layernorm_k(const float* __restrict__ y, const float* __restrict__ gamma,
                            const float* __restrict__ beta, float* __restrict__ out) {
    int row = blockIdx.x;
    int t = threadIdx.x;
    const float4* p = reinterpret_cast<const float4*>(y + (size_t)row * 512);
    float4 v = p[t];
    float s = v.x + v.y + v.z + v.w;
#pragma unroll
    for (int o = 16; o; o >>= 1) s += __shfl_xor_sync(0xffffffffu, s, o);
    __shared__ float sm[4];
    if ((t & 31) == 0) sm[t >> 5] = s;
    __syncthreads();
    float mu = (sm[0] + sm[1] + sm[2] + sm[3]) * (1.0f / 512.0f);
    float dx = v.x - mu, dy = v.y - mu, dz = v.z - mu, dw = v.w - mu;
    float q = dx * dx + dy * dy + dz * dz + dw * dw;
#pragma unroll
    for (int o = 16; o; o >>= 1) q += __shfl_xor_sync(0xffffffffu, q, o);
    __shared__ float sq[4];
    if ((t & 31) == 0) sq[t >> 5] = q;
    __syncthreads();
    float var = (sq[0] + sq[1] + sq[2] + sq[3]) * (1.0f / 512.0f);
    float rs = rsqrtf(var + 1e-6f);
    float4 g = reinterpret_cast<const float4*>(gamma)[t];
    float4 b = reinterpret_cast<const float4*>(beta)[t];
    float4 r;
    r.x = dx * rs * g.x + b.x;
    r.y = dy * rs * g.y + b.y;
    r.z = dz * rs * g.z + b.z;
    r.w = dw * rs * g.w + b.w;
    reinterpret_cast<float4*>(out + (size_t)row * 512)[t] = r;
}

// ---------------------------------------------------------------
extern "C" void kernel_launch(void* const* d_in, const int* in_sizes, int n_in,
                              void* d_out, int out_size) {
    const float* x     = (const float*)d_in[0];
    const float* Wq    = (const float*)d_in[1];
    const float* Wk    = (const float*)d_in[2];
    const float* Wv    = (const float*)d_in[3];
    const float* Wo    = (const float*)d_in[4];
    const float* bo    = (const float*)d_in[5];
    const float* gamma = (const float*)d_in[6];
    const float* beta  = (const float*)d_in[7];
    float* out = (float*)d_out;

    bf16 *xb, *qkb, *wqkt, *wvt, *wot, *vt, *ob;
    float *yb;
    cudaGetSymbolAddress((void**)&xb,   g_xb);
    cudaGetSymbolAddress((void**)&qkb,  g_qkb);
    cudaGetSymbolAddress((void**)&wqkt, g_wqkt);
    cudaGetSymbolAddress((void**)&wvt,  g_wvt);
    cudaGetSymbolAddress((void**)&wot,  g_wot);
    cudaGetSymbolAddress((void**)&vt,   g_vt);
    cudaGetSymbolAddress((void**)&ob,   g_ob);
    cudaGetSymbolAddress((void**)&yb,   g_y);

    cudaFuncSetAttribute(flash_attn_k, cudaFuncAttributeMaxDynamicSharedMemorySize, FLASH_SMEM);
    cudaFuncSetAttribute(gemm_qkvt, cudaFuncAttributeMaxDynamicSharedMemorySize, GEMM_SMEM);
    cudaFuncSetAttribute(gemm_wo,   cudaFuncAttributeMaxDynamicSharedMemorySize, GEMM_SMEM);

    // 1) fused prep: x->bf16 + all weight transposes
    prep_k<<<8704, 256>>>(x, xb, Wq, Wk, Wv, Wo, wqkt, wvt, wot);
    // 2) fused [q|k] projection + Vt (z=0: qk; z>=1: Vt batch z-1)
    gemm_qkvt<<<dim3(8, 64, 9), 256, GEMM_SMEM>>>(xb, wqkt, qkb, wvt, vt);
    // 3) fused attention: scores + mask + softmax + P·V -> ob  (d-chunk 256)
    flash_attn_k<<<dim3(16, 64), 256, FLASH_SMEM>>>(qkb, vt, ob);
    // 4) y = o @ Wo + bo + x
    gemm_wo<<<dim3(4, 64, 1), 256, GEMM_SMEM>>>(ob, wot, yb, bo, x);
    // 5) LayerNorm -> out
    layernorm_k<<<8192, 128>>>(yb, gamma, beta, out);
}